// round 5
// baseline (speedup 1.0000x reference)
#include <cuda_runtime.h>
#include <cuda_bf16.h>
#include <math.h>
#include <stdint.h>

#define DM   1024
#define NH   16
#define DFF  4096
#define BB   8
#define SS   1024
#define MTOK (BB*SS)
#define KP3   (3*DM)    // 3072
#define KP3FF (3*DFF)   // 12288

// ---------------- scratch ----------------
__device__ float g_x0  [MTOK*DM];
__device__ float g_qkv [MTOK*3*DM];
__device__ float g_proj[MTOK*DM];
__device__ float g_x1  [MTOK*DM];
__device__ float g_ffn [MTOK*DM];
__device__ __nv_bfloat16 g_x0s  [(size_t)MTOK*KP3];
__device__ __nv_bfloat16 g_attns[(size_t)MTOK*KP3];
__device__ __nv_bfloat16 g_x1s  [(size_t)MTOK*KP3];
__device__ __nv_bfloat16 g_hs   [(size_t)MTOK*KP3FF];
__device__ __nv_bfloat16 g_wqkvs[(size_t)(3*DM)*KP3];
__device__ __nv_bfloat16 g_wouts[(size_t)DM*KP3];
__device__ __nv_bfloat16 g_w1s  [(size_t)DFF*KP3];
__device__ __nv_bfloat16 g_w2s  [(size_t)DM*KP3FF];

// ---------------- asm helpers ----------------
__device__ __forceinline__ uint32_t smem_u32(const void* p) {
    uint32_t a;
    asm("{ .reg .u64 t; cvta.to.shared.u64 t, %1; cvt.u32.u64 %0, t; }" : "=r"(a) : "l"(p));
    return a;
}
#define CP_ASYNC16(saddr, gptr) \
    asm volatile("cp.async.cg.shared.global [%0], [%1], 16;" :: "r"(saddr), "l"(gptr))
#define CP_COMMIT() asm volatile("cp.async.commit_group;" ::: "memory")
#define CP_WAIT2()  asm volatile("cp.async.wait_group 2;" ::: "memory")
#define CP_WAIT0()  asm volatile("cp.async.wait_group 0;" ::: "memory")

#define LDM_X4(r0, r1, r2, r3, a) \
    asm volatile("ldmatrix.sync.aligned.m8n8.x4.shared.b16 {%0,%1,%2,%3}, [%4];" \
                 : "=r"(r0), "=r"(r1), "=r"(r2), "=r"(r3) : "r"(a))
#define LDM_X2(r0, r1, a) \
    asm volatile("ldmatrix.sync.aligned.m8n8.x2.shared.b16 {%0,%1}, [%2];" \
                 : "=r"(r0), "=r"(r1) : "r"(a))

#define MMA_BF16(d, a0, a1, a2, a3, b0, b1) \
    asm volatile("mma.sync.aligned.m16n8k16.row.col.f32.bf16.bf16.f32 " \
                 "{%0,%1,%2,%3}, {%4,%5,%6,%7}, {%8,%9}, {%0,%1,%2,%3};" \
                 : "+f"((d)[0]), "+f"((d)[1]), "+f"((d)[2]), "+f"((d)[3]) \
                 : "r"(a0), "r"(a1), "r"(a2), "r"(a3), "r"(b0), "r"(b1))

__device__ __forceinline__ float gelu_exact(float v) {
    return 0.5f * v * (1.0f + erff(v * 0.70710678118654752f));
}

// ---------------- GEMM via mma.sync (bf16, f32 accum) --------------------
// C[M,N] = A''[M,Kp] x B''t[N,Kp]. CTA 256x128, BK=32, 16 warps of 64x32.
// smem rows padded to 40 bf16 (80B stride) -> conflict-free ldmatrix.
#define STG_A   (256 * 80)          // bytes per A tile per stage
#define STG_Bb  (128 * 80)          // bytes per B tile per stage
#define STG_T   (STG_A + STG_Bb)    // 30720
#define NSTAGE  4
#define GSMEM   (NSTAGE * STG_T)    // 122880 bytes

template <int ACT>
__global__ void __launch_bounds__(512, 1)
gemm_mma(const __nv_bfloat16* __restrict__ A, const __nv_bfloat16* __restrict__ B,
         const float* __restrict__ bias, float* __restrict__ Cf,
         __nv_bfloat16* __restrict__ Cs, int Ndim, int Kp, int cs_slab)
{
    extern __shared__ __align__(128) char smem[];
    const uint32_t sA = smem_u32(smem);
    const uint32_t sB = sA + NSTAGE * STG_A;

    const int tid  = threadIdx.x;
    const int lane = tid & 31;
    const int wid  = tid >> 5;
    const int wm   = wid & 3;        // M quarter (64 rows)
    const int wn   = wid >> 2;       // N quarter (32 cols)
    const int row0 = blockIdx.y * 256;
    const int n0   = blockIdx.x * 128;

    // cp.async mapping: tid>>2 = row 0..127; (tid&3)*16 = byte chunk in 64B k-slab
    const int ldr0 = tid >> 2;
    const int ldkc = (tid & 3) * 16;
    const __nv_bfloat16* gA = A + (size_t)(row0 + ldr0) * Kp;
    const __nv_bfloat16* gB = B + (size_t)(n0  + ldr0) * Kp;
    const size_t aRow128 = (size_t)128 * Kp;

    // ldmatrix source addresses (per stage add stage offset)
    const uint32_t aLd = sA + (wm * 64 + (lane & 15)) * 80 + (lane >> 4) * 16;
    const uint32_t bLd = sB + (wn * 32 + (lane & 7)) * 80 + ((lane >> 3) & 1) * 16;

    float d[4][4][4];
#pragma unroll
    for (int i = 0; i < 4; i++)
#pragma unroll
        for (int j = 0; j < 4; j++)
#pragma unroll
            for (int c = 0; c < 4; c++) d[i][j][c] = 0.f;

    const int kTiles = Kp >> 5;   // BK=32

    // prefetch stages 0..2
#pragma unroll
    for (int s = 0; s < 3; s++) {
        const int k0 = s * 32;
        uint32_t dA = sA + s * STG_A + ldr0 * 80 + ldkc;
        uint32_t dB = sB + s * STG_Bb + ldr0 * 80 + ldkc;
        CP_ASYNC16(dA,               (const char*)(gA + k0) + ldkc);
        CP_ASYNC16(dA + 128 * 80,    (const char*)(gA + aRow128 + k0) + ldkc);
        CP_ASYNC16(dB,               (const char*)(gB + k0) + ldkc);
        CP_COMMIT();
    }

    for (int kt = 0; kt < kTiles; kt++) {
        CP_WAIT2();
        __syncthreads();

        // prefetch stage kt+3
        if (kt + 3 < kTiles) {
            const int s = (kt + 3) & (NSTAGE - 1);
            const int k0 = (kt + 3) * 32;
            uint32_t dA = sA + s * STG_A + ldr0 * 80 + ldkc;
            uint32_t dB = sB + s * STG_Bb + ldr0 * 80 + ldkc;
            CP_ASYNC16(dA,            (const char*)(gA + k0) + ldkc);
            CP_ASYNC16(dA + 128 * 80, (const char*)(gA + aRow128 + k0) + ldkc);
            CP_ASYNC16(dB,            (const char*)(gB + k0) + ldkc);
        }
        CP_COMMIT();

        const int st = kt & (NSTAGE - 1);
        const uint32_t aS = aLd + st * STG_A;
        const uint32_t bS = bLd + st * STG_Bb;
#pragma unroll
        for (int k16 = 0; k16 < 2; k16++) {
            uint32_t a[4][4], b[4][2];
#pragma unroll
            for (int mt = 0; mt < 4; mt++)
                LDM_X4(a[mt][0], a[mt][1], a[mt][2], a[mt][3],
                       aS + mt * (16 * 80) + k16 * 32);
#pragma unroll
            for (int nt = 0; nt < 4; nt++)
                LDM_X2(b[nt][0], b[nt][1], bS + nt * (8 * 80) + k16 * 32);
#pragma unroll
            for (int mt = 0; mt < 4; mt++)
#pragma unroll
                for (int nt = 0; nt < 4; nt++)
                    MMA_BF16(d[mt][nt], a[mt][0], a[mt][1], a[mt][2], a[mt][3],
                             b[nt][0], b[nt][1]);
        }
    }
    CP_WAIT0();

    // ---- epilogue ----
#pragma unroll
    for (int mt = 0; mt < 4; mt++) {
#pragma unroll
        for (int half = 0; half < 2; half++) {
            const int row = row0 + wm * 64 + mt * 16 + (lane >> 2) + half * 8;
#pragma unroll
            for (int nt = 0; nt < 4; nt++) {
                const int col = n0 + wn * 32 + nt * 8 + (lane & 3) * 2;
                float v0 = d[mt][nt][half * 2 + 0] + bias[col];
                float v1 = d[mt][nt][half * 2 + 1] + bias[col + 1];
                if (ACT == 0) {
                    float2 o; o.x = v0; o.y = v1;
                    *(float2*)&Cf[(size_t)row * Ndim + col] = o;
                } else {
                    v0 = gelu_exact(v0);
                    v1 = gelu_exact(v1);
                    __nv_bfloat16 h0 = __float2bfloat16(v0);
                    __nv_bfloat16 h1 = __float2bfloat16(v1);
                    __nv_bfloat162 hp; hp.x = h0; hp.y = h1;
                    __nv_bfloat162 lp;
                    lp.x = __float2bfloat16(v0 - __bfloat162float(h0));
                    lp.y = __float2bfloat16(v1 - __bfloat162float(h1));
                    const size_t ro = (size_t)row * (size_t)(3 * cs_slab);
                    *(__nv_bfloat162*)&Cs[ro + col]               = hp;
                    *(__nv_bfloat162*)&Cs[ro + cs_slab + col]     = hp;
                    *(__nv_bfloat162*)&Cs[ro + 2 * cs_slab + col] = lp;
                }
            }
        }
    }
}

// ---------------- weight transpose + split: W[K,N] -> Wt''[N,3K] = [hi|lo|hi] -----
__global__ void wconv_kernel(const float* __restrict__ W, __nv_bfloat16* __restrict__ Wt,
                             int K, int N)
{
    __shared__ float t[32][33];
    const int n0 = blockIdx.x * 32, k0 = blockIdx.y * 32;
    for (int i = threadIdx.y; i < 32; i += 8)
        t[i][threadIdx.x] = W[(size_t)(k0 + i) * N + n0 + threadIdx.x];
    __syncthreads();
    for (int i = threadIdx.y; i < 32; i += 8) {
        int n = n0 + i, k = k0 + threadIdx.x;
        float v = t[threadIdx.x][i];
        __nv_bfloat16 hv = __float2bfloat16(v);
        __nv_bfloat16 lv = __float2bfloat16(v - __bfloat162float(hv));
        size_t ro = (size_t)n * (size_t)(3 * K);
        Wt[ro + k] = hv;
        Wt[ro + K + k] = lv;
        Wt[ro + 2 * K + k] = hv;
    }
}

// ---------------- add step embed + split: A'' = [hi|hi|lo] ----------------
__global__ void add_step_kernel(const float* __restrict__ x, const float* __restrict__ se,
                                const int* __restrict__ ts, float* __restrict__ x0,
                                __nv_bfloat16* __restrict__ xs)
{
    int i = blockIdx.x * blockDim.x + threadIdx.x;
    int step = ts[0];
    if (step > 15) step = 15;
    if (step < 0) step += 16;
    int k = i & (DM - 1);
    float v = x[i] + se[step * DM + k];
    x0[i] = v;
    __nv_bfloat16 h = __float2bfloat16(v);
    __nv_bfloat16 lo = __float2bfloat16(v - __bfloat162float(h));
    size_t ro = (size_t)(i >> 10) * KP3;
    xs[ro + k] = h;
    xs[ro + DM + k] = h;
    xs[ro + 2 * DM + k] = lo;
}

// ---------------- flash attention (fp32), epilogue writes bf16 splits -------------
__global__ void __launch_bounds__(256)
attn_kernel(const float* __restrict__ qkv, const float* __restrict__ rpb,
            __nv_bfloat16* __restrict__ outs)
{
    __shared__ __align__(16) float Qs[32 * 65];
    __shared__ __align__(16) float KPs[64 * 65];
    __shared__ __align__(16) float Vs[64 * 66];
    __shared__ float rb[127];

    const int tid = threadIdx.x;
    const int qt = blockIdx.x;
    const int h  = blockIdx.y;
    const int b  = blockIdx.z;
    const int tc = tid & 31;
    const int tr = tid >> 5;

    if (tid < 127) rb[tid] = rpb[tid];
    const int qbase = qt * 32;
    const float scale = 0.125f;

    for (int t = tid; t < 32 * 64; t += 256) {
        int r = t >> 6, c = t & 63;
        Qs[r * 65 + c] = qkv[((size_t)(b * SS + qbase + r)) * 3072 + h * 64 + c] * scale;
    }

    float m[4], l[4], acc[4][2];
#pragma unroll
    for (int i = 0; i < 4; i++) { m[i] = -1e30f; l[i] = 0.f; acc[i][0] = 0.f; acc[i][1] = 0.f; }

    for (int kt = 0; kt < 16; kt++) {
        const int kbase = kt * 64;
        __syncthreads();
        for (int t = tid; t < 64 * 64; t += 256) {
            int r = t >> 6, c = t & 63;
            size_t base = ((size_t)(b * SS + kbase + r)) * 3072 + h * 64 + c;
            KPs[r * 65 + c] = qkv[base + 1024];
            Vs [r * 66 + c] = qkv[base + 2048];
        }
        __syncthreads();

        float s0[4] = {0.f, 0.f, 0.f, 0.f};
        float s1[4] = {0.f, 0.f, 0.f, 0.f};
#pragma unroll 4
        for (int dd = 0; dd < 64; dd++) {
            float k0v = KPs[tc * 65 + dd];
            float k1v = KPs[(tc + 32) * 65 + dd];
#pragma unroll
            for (int i = 0; i < 4; i++) {
                float qv = Qs[(tr * 4 + i) * 65 + dd];
                s0[i] += qv * k0v;
                s1[i] += qv * k1v;
            }
        }
#pragma unroll
        for (int i = 0; i < 4; i++) {
            int qg = qbase + tr * 4 + i;
            int r0 = qg - (kbase + tc) + 63;       r0 = min(max(r0, 0), 126);
            int r1 = qg - (kbase + tc + 32) + 63;  r1 = min(max(r1, 0), 126);
            s0[i] += rb[r0];
            s1[i] += rb[r1];
        }
        __syncthreads();

#pragma unroll
        for (int i = 0; i < 4; i++) {
            float mt = fmaxf(s0[i], s1[i]);
#pragma unroll
            for (int o = 16; o > 0; o >>= 1) mt = fmaxf(mt, __shfl_xor_sync(0xffffffffu, mt, o));
            float mn = fmaxf(m[i], mt);
            float ci = __expf(m[i] - mn);
            float p0 = __expf(s0[i] - mn);
            float p1 = __expf(s1[i] - mn);
            float ls = p0 + p1;
#pragma unroll
            for (int o = 16; o > 0; o >>= 1) ls += __shfl_xor_sync(0xffffffffu, ls, o);
            l[i] = l[i] * ci + ls;
            m[i] = mn;
            acc[i][0] *= ci; acc[i][1] *= ci;
            KPs[(tr * 4 + i) * 65 + tc]      = p0;
            KPs[(tr * 4 + i) * 65 + tc + 32] = p1;
        }
        __syncthreads();

        const int d0 = tc * 2;
#pragma unroll 4
        for (int k = 0; k < 64; k++) {
            float2 v = *(const float2*)&Vs[k * 66 + d0];
#pragma unroll
            for (int i = 0; i < 4; i++) {
                float p = KPs[(tr * 4 + i) * 65 + k];
                acc[i][0] += p * v.x;
                acc[i][1] += p * v.y;
            }
        }
    }

#pragma unroll
    for (int i = 0; i < 4; i++) {
        float inv = 1.f / l[i];
        float v0 = acc[i][0] * inv, v1 = acc[i][1] * inv;
        size_t ro = (size_t)(b * SS + qbase + tr * 4 + i) * KP3;
        int n = h * 64 + tc * 2;
        __nv_bfloat16 h0 = __float2bfloat16(v0);
        __nv_bfloat16 h1 = __float2bfloat16(v1);
        __nv_bfloat162 hp; hp.x = h0; hp.y = h1;
        __nv_bfloat162 lp;
        lp.x = __float2bfloat16(v0 - __bfloat162float(h0));
        lp.y = __float2bfloat16(v1 - __bfloat162float(h1));
        *(__nv_bfloat162*)&outs[ro + n]          = hp;
        *(__nv_bfloat162*)&outs[ro + DM + n]     = hp;
        *(__nv_bfloat162*)&outs[ro + 2 * DM + n] = lp;
    }
}

// ---------------- residual + layernorm (SPLIT=1: also write bf16 splits) ---------
template <int SPLIT>
__global__ void __launch_bounds__(256)
ln_res_kernel(const float* __restrict__ a, const float* __restrict__ r,
              const float* __restrict__ g, const float* __restrict__ bt,
              float* __restrict__ out, __nv_bfloat16* __restrict__ outs)
{
    __shared__ float red[8];
    const int row = blockIdx.x;
    const int tid = threadIdx.x;
    const float* pa = a + (size_t)row * DM;
    const float* pr = r + (size_t)row * DM;

    float v[4];
    float sum = 0.f;
#pragma unroll
    for (int j = 0; j < 4; j++) {
        int c = tid + j * 256;
        v[j] = pa[c] + pr[c];
        sum += v[j];
    }
#pragma unroll
    for (int o = 16; o > 0; o >>= 1) sum += __shfl_xor_sync(0xffffffffu, sum, o);
    if ((tid & 31) == 0) red[tid >> 5] = sum;
    __syncthreads();
    float tot = 0.f;
#pragma unroll
    for (int w = 0; w < 8; w++) tot += red[w];
    const float mean = tot * (1.f / (float)DM);

    float sq = 0.f;
#pragma unroll
    for (int j = 0; j < 4; j++) { float dd = v[j] - mean; sq += dd * dd; }
    __syncthreads();
#pragma unroll
    for (int o = 16; o > 0; o >>= 1) sq += __shfl_xor_sync(0xffffffffu, sq, o);
    if ((tid & 31) == 0) red[tid >> 5] = sq;
    __syncthreads();
    float vtot = 0.f;
#pragma unroll
    for (int w = 0; w < 8; w++) vtot += red[w];
    const float inv = rsqrtf(vtot * (1.f / (float)DM) + 1e-5f);

#pragma unroll
    for (int j = 0; j < 4; j++) {
        int c = tid + j * 256;
        float o = (v[j] - mean) * inv * g[c] + bt[c];
        out[(size_t)row * DM + c] = o;
        if (SPLIT) {
            __nv_bfloat16 h = __float2bfloat16(o);
            __nv_bfloat16 lo = __float2bfloat16(o - __bfloat162float(h));
            size_t ro = (size_t)row * KP3;
            outs[ro + c] = h;
            outs[ro + DM + c] = h;
            outs[ro + 2 * DM + c] = lo;
        }
    }
}

// ---------------- host ----------------
extern "C" void kernel_launch(void* const* d_in, const int* in_sizes, int n_in,
                              void* d_out, int out_size)
{
    const float* x     = (const float*)d_in[0];
    const float* se    = (const float*)d_in[1];
    const float* qkv_w = (const float*)d_in[2];
    const float* qkv_b = (const float*)d_in[3];
    const float* out_w = (const float*)d_in[4];
    const float* out_b = (const float*)d_in[5];
    const float* rpb   = (const float*)d_in[6];
    const float* w1    = (const float*)d_in[7];
    const float* b1    = (const float*)d_in[8];
    const float* w2    = (const float*)d_in[9];
    const float* b2    = (const float*)d_in[10];
    const float* ln1g  = (const float*)d_in[11];
    const float* ln1b  = (const float*)d_in[12];
    const float* ln2g  = (const float*)d_in[13];
    const float* ln2b  = (const float*)d_in[14];
    const int*   ts    = (const int*)d_in[15];
    float* out = (float*)d_out;

    float *x0, *qkv, *proj, *x1, *ffn;
    __nv_bfloat16 *x0s, *attns, *x1s, *hs, *wqkvs, *wouts, *w1s, *w2s;
    cudaGetSymbolAddress((void**)&x0,   g_x0);
    cudaGetSymbolAddress((void**)&qkv,  g_qkv);
    cudaGetSymbolAddress((void**)&proj, g_proj);
    cudaGetSymbolAddress((void**)&x1,   g_x1);
    cudaGetSymbolAddress((void**)&ffn,  g_ffn);
    cudaGetSymbolAddress((void**)&x0s,   g_x0s);
    cudaGetSymbolAddress((void**)&attns, g_attns);
    cudaGetSymbolAddress((void**)&x1s,   g_x1s);
    cudaGetSymbolAddress((void**)&hs,    g_hs);
    cudaGetSymbolAddress((void**)&wqkvs, g_wqkvs);
    cudaGetSymbolAddress((void**)&wouts, g_wouts);
    cudaGetSymbolAddress((void**)&w1s,   g_w1s);
    cudaGetSymbolAddress((void**)&w2s,   g_w2s);

    cudaFuncSetAttribute(gemm_mma<0>, cudaFuncAttributeMaxDynamicSharedMemorySize, GSMEM);
    cudaFuncSetAttribute(gemm_mma<1>, cudaFuncAttributeMaxDynamicSharedMemorySize, GSMEM);

    // weight conversions (transpose + hi/lo split)
    wconv_kernel<<<dim3(3 * DM / 32, DM / 32),  dim3(32, 8)>>>(qkv_w, wqkvs, DM, 3 * DM);
    wconv_kernel<<<dim3(DM / 32, DM / 32),      dim3(32, 8)>>>(out_w, wouts, DM, DM);
    wconv_kernel<<<dim3(DFF / 32, DM / 32),     dim3(32, 8)>>>(w1, w1s, DM, DFF);
    wconv_kernel<<<dim3(DM / 32, DFF / 32),     dim3(32, 8)>>>(w2, w2s, DFF, DM);

    // 1) x0 = x + step_embed ; split
    add_step_kernel<<<(MTOK * DM) / 256, 256>>>(x, se, ts, x0, x0s);

    // 2) qkv = x0 @ qkv_w + b
    gemm_mma<0><<<dim3(3 * DM / 128, MTOK / 256), 512, GSMEM>>>(
        x0s, wqkvs, qkv_b, qkv, nullptr, 3 * DM, KP3, 0);

    // 3) attention -> attns (split)
    attn_kernel<<<dim3(SS / 32, NH, BB), 256>>>(qkv, rpb, attns);

    // 4) proj = attn @ out_w + b
    gemm_mma<0><<<dim3(DM / 128, MTOK / 256), 512, GSMEM>>>(
        attns, wouts, out_b, proj, nullptr, DM, KP3, 0);

    // 5) x1 = LN(x0 + proj) ; split
    ln_res_kernel<1><<<MTOK, 256>>>(x0, proj, ln1g, ln1b, x1, x1s);

    // 6) h = gelu(x1 @ w1 + b1) -> hs (split)
    gemm_mma<1><<<dim3(DFF / 128, MTOK / 256), 512, GSMEM>>>(
        x1s, w1s, b1, nullptr, hs, DFF, KP3, DFF);

    // 7) ffn = h @ w2 + b2
    gemm_mma<0><<<dim3(DM / 128, MTOK / 256), 512, GSMEM>>>(
        hs, w2s, b2, ffn, nullptr, DM, KP3FF, 0);

    // 8) out = LN(x1 + ffn)
    ln_res_kernel<0><<<MTOK, 256>>>(x1, ffn, ln2g, ln2b, out, nullptr);
}

// round 6
// speedup vs baseline: 1.4115x; 1.4115x over previous
#include <cuda_runtime.h>
#include <cuda_bf16.h>
#include <math.h>
#include <stdint.h>

#define DM   1024
#define NH   16
#define DFF  4096
#define BB   8
#define SS   1024
#define MTOK (BB*SS)
#define KP3   (3*DM)    // 3072
#define KP3FF (3*DFF)   // 12288

// ---------------- scratch ----------------
__device__ float g_x0  [MTOK*DM];
__device__ float g_qkv [MTOK*3*DM];
__device__ float g_proj[MTOK*DM];
__device__ float g_x1  [MTOK*DM];
__device__ float g_ffn [MTOK*DM];
__device__ __nv_bfloat16 g_x0s  [(size_t)MTOK*KP3];
__device__ __nv_bfloat16 g_attns[(size_t)MTOK*KP3];
__device__ __nv_bfloat16 g_x1s  [(size_t)MTOK*KP3];
__device__ __nv_bfloat16 g_hs   [(size_t)MTOK*KP3FF];
__device__ __nv_bfloat16 g_wqkvs[(size_t)(3*DM)*KP3];
__device__ __nv_bfloat16 g_wouts[(size_t)DM*KP3];
__device__ __nv_bfloat16 g_w1s  [(size_t)DFF*KP3];
__device__ __nv_bfloat16 g_w2s  [(size_t)DM*KP3FF];

// ---------------- asm helpers ----------------
__device__ __forceinline__ uint32_t smem_u32(const void* p) {
    uint32_t a;
    asm("{ .reg .u64 t; cvta.to.shared.u64 t, %1; cvt.u32.u64 %0, t; }" : "=r"(a) : "l"(p));
    return a;
}
#define CP_ASYNC16(saddr, gptr) \
    asm volatile("cp.async.cg.shared.global [%0], [%1], 16;" :: "r"(saddr), "l"(gptr))
#define CP_COMMIT() asm volatile("cp.async.commit_group;" ::: "memory")
#define CP_WAIT1()  asm volatile("cp.async.wait_group 1;" ::: "memory")
#define CP_WAIT0()  asm volatile("cp.async.wait_group 0;" ::: "memory")

#define LDM_X4(r0, r1, r2, r3, a) \
    asm volatile("ldmatrix.sync.aligned.m8n8.x4.shared.b16 {%0,%1,%2,%3}, [%4];" \
                 : "=r"(r0), "=r"(r1), "=r"(r2), "=r"(r3) : "r"(a))
#define LDM_X4T(r0, r1, r2, r3, a) \
    asm volatile("ldmatrix.sync.aligned.m8n8.x4.trans.shared.b16 {%0,%1,%2,%3}, [%4];" \
                 : "=r"(r0), "=r"(r1), "=r"(r2), "=r"(r3) : "r"(a))
#define LDM_X2(r0, r1, a) \
    asm volatile("ldmatrix.sync.aligned.m8n8.x2.shared.b16 {%0,%1}, [%2];" \
                 : "=r"(r0), "=r"(r1) : "r"(a))

#define MMA_BF16(d, a0, a1, a2, a3, b0, b1) \
    asm volatile("mma.sync.aligned.m16n8k16.row.col.f32.bf16.bf16.f32 " \
                 "{%0,%1,%2,%3}, {%4,%5,%6,%7}, {%8,%9}, {%0,%1,%2,%3};" \
                 : "+f"((d)[0]), "+f"((d)[1]), "+f"((d)[2]), "+f"((d)[3]) \
                 : "r"(a0), "r"(a1), "r"(a2), "r"(a3), "r"(b0), "r"(b1))

__device__ __forceinline__ float gelu_exact(float v) {
    return 0.5f * v * (1.0f + erff(v * 0.70710678118654752f));
}
__device__ __forceinline__ uint32_t pack_bf162(float lo, float hi) {
    __nv_bfloat162 t = __floats2bfloat162_rn(lo, hi);
    return *(uint32_t*)&t;
}

// ---------------- GEMM via mma.sync (round-4 proven config) --------------------
// C[M,N] = A''[M,Kp] x B''t[N,Kp]. CTA 128x128, BK=32, 8 warps of 64x32.
#define STG_E   (128 * 40)
#define STG_B   (STG_E * 2)         // 10240 bytes
#define NSTAGE  3
#define GSMEM   (NSTAGE * STG_B * 2)  // 61440 bytes

template <int ACT>
__global__ void __launch_bounds__(256, 2)
gemm_mma(const __nv_bfloat16* __restrict__ A, const __nv_bfloat16* __restrict__ B,
         const float* __restrict__ bias, float* __restrict__ Cf,
         __nv_bfloat16* __restrict__ Cs, int Ndim, int Kp, int cs_slab)
{
    extern __shared__ __align__(128) char smem[];
    const uint32_t sA = smem_u32(smem);
    const uint32_t sB = sA + NSTAGE * STG_B;

    const int tid  = threadIdx.x;
    const int lane = tid & 31;
    const int wid  = tid >> 5;
    const int wm   = wid & 1;
    const int wn   = wid >> 1;
    const int row0 = blockIdx.y * 128;
    const int n0   = blockIdx.x * 128;

    const int ldr0 = tid >> 2;
    const int ldkc = (tid & 3) * 16;
    const __nv_bfloat16* gA = A + (size_t)(row0 + ldr0) * Kp;
    const __nv_bfloat16* gB = B + (size_t)(n0  + ldr0) * Kp;

    const uint32_t aLd = sA + ((wm * 64 + (lane & 15)) * 40 + (lane >> 4) * 8) * 2;
    const uint32_t bLd = sB + ((wn * 32 + (lane & 7)) * 40 + ((lane >> 3) & 1) * 8) * 2;

    float d[4][4][4];
#pragma unroll
    for (int i = 0; i < 4; i++)
#pragma unroll
        for (int j = 0; j < 4; j++)
#pragma unroll
            for (int c = 0; c < 4; c++) d[i][j][c] = 0.f;

    const int kTiles = Kp >> 5;

#pragma unroll
    for (int s = 0; s < 2; s++) {
        const int k0 = s * 32;
#pragma unroll
        for (int i = 0; i < 2; i++) {
            int r = ldr0 + i * 64;
            uint32_t dstA = sA + s * STG_B + r * 80 + ldkc;
            uint32_t dstB = sB + s * STG_B + r * 80 + ldkc;
            CP_ASYNC16(dstA, (const char*)(gA + (size_t)i * 64 * Kp + k0) + ldkc);
            CP_ASYNC16(dstB, (const char*)(gB + (size_t)i * 64 * Kp + k0) + ldkc);
        }
        CP_COMMIT();
    }

    for (int kt = 0; kt < kTiles; kt++) {
        CP_WAIT1();
        __syncthreads();

        if (kt + 2 < kTiles) {
            const int s = (kt + 2) % NSTAGE;
            const int k0 = (kt + 2) * 32;
#pragma unroll
            for (int i = 0; i < 2; i++) {
                int r = ldr0 + i * 64;
                uint32_t dstA = sA + s * STG_B + r * 80 + ldkc;
                uint32_t dstB = sB + s * STG_B + r * 80 + ldkc;
                CP_ASYNC16(dstA, (const char*)(gA + (size_t)i * 64 * Kp + k0) + ldkc);
                CP_ASYNC16(dstB, (const char*)(gB + (size_t)i * 64 * Kp + k0) + ldkc);
            }
        }
        CP_COMMIT();

        const uint32_t aS = aLd + (kt % NSTAGE) * STG_B;
        const uint32_t bS = bLd + (kt % NSTAGE) * STG_B;
#pragma unroll
        for (int k16 = 0; k16 < 2; k16++) {
            uint32_t a[4][4], b[4][2];
#pragma unroll
            for (int mt = 0; mt < 4; mt++)
                LDM_X4(a[mt][0], a[mt][1], a[mt][2], a[mt][3],
                       aS + mt * (16 * 80) + k16 * 32);
#pragma unroll
            for (int nt = 0; nt < 4; nt++)
                LDM_X2(b[nt][0], b[nt][1], bS + nt * (8 * 80) + k16 * 32);
#pragma unroll
            for (int mt = 0; mt < 4; mt++)
#pragma unroll
                for (int nt = 0; nt < 4; nt++)
                    MMA_BF16(d[mt][nt], a[mt][0], a[mt][1], a[mt][2], a[mt][3],
                             b[nt][0], b[nt][1]);
        }
    }
    CP_WAIT0();

#pragma unroll
    for (int mt = 0; mt < 4; mt++) {
#pragma unroll
        for (int half = 0; half < 2; half++) {
            const int row = row0 + wm * 64 + mt * 16 + (lane >> 2) + half * 8;
#pragma unroll
            for (int nt = 0; nt < 4; nt++) {
                const int col = n0 + wn * 32 + nt * 8 + (lane & 3) * 2;
                float v0 = d[mt][nt][half * 2 + 0] + bias[col];
                float v1 = d[mt][nt][half * 2 + 1] + bias[col + 1];
                if (ACT == 0) {
                    float2 o; o.x = v0; o.y = v1;
                    *(float2*)&Cf[(size_t)row * Ndim + col] = o;
                } else {
                    v0 = gelu_exact(v0);
                    v1 = gelu_exact(v1);
                    __nv_bfloat16 h0 = __float2bfloat16(v0);
                    __nv_bfloat16 h1 = __float2bfloat16(v1);
                    __nv_bfloat162 hp; hp.x = h0; hp.y = h1;
                    __nv_bfloat162 lp;
                    lp.x = __float2bfloat16(v0 - __bfloat162float(h0));
                    lp.y = __float2bfloat16(v1 - __bfloat162float(h1));
                    const size_t ro = (size_t)row * (size_t)(3 * cs_slab);
                    *(__nv_bfloat162*)&Cs[ro + col]               = hp;
                    *(__nv_bfloat162*)&Cs[ro + cs_slab + col]     = hp;
                    *(__nv_bfloat162*)&Cs[ro + 2 * cs_slab + col] = lp;
                }
            }
        }
    }
}

// ---------------- weight transpose + split ----------------
__global__ void wconv_kernel(const float* __restrict__ W, __nv_bfloat16* __restrict__ Wt,
                             int K, int N)
{
    __shared__ float t[32][33];
    const int n0 = blockIdx.x * 32, k0 = blockIdx.y * 32;
    for (int i = threadIdx.y; i < 32; i += 8)
        t[i][threadIdx.x] = W[(size_t)(k0 + i) * N + n0 + threadIdx.x];
    __syncthreads();
    for (int i = threadIdx.y; i < 32; i += 8) {
        int n = n0 + i, k = k0 + threadIdx.x;
        float v = t[threadIdx.x][i];
        __nv_bfloat16 hv = __float2bfloat16(v);
        __nv_bfloat16 lv = __float2bfloat16(v - __bfloat162float(hv));
        size_t ro = (size_t)n * (size_t)(3 * K);
        Wt[ro + k] = hv;
        Wt[ro + K + k] = lv;
        Wt[ro + 2 * K + k] = hv;
    }
}

// ---------------- add step embed + split ----------------
__global__ void add_step_kernel(const float* __restrict__ x, const float* __restrict__ se,
                                const int* __restrict__ ts, float* __restrict__ x0,
                                __nv_bfloat16* __restrict__ xs)
{
    int i = blockIdx.x * blockDim.x + threadIdx.x;
    int step = ts[0];
    if (step > 15) step = 15;
    if (step < 0) step += 16;
    int k = i & (DM - 1);
    float v = x[i] + se[step * DM + k];
    x0[i] = v;
    __nv_bfloat16 h = __float2bfloat16(v);
    __nv_bfloat16 lo = __float2bfloat16(v - __bfloat162float(h));
    size_t ro = (size_t)(i >> 10) * KP3;
    xs[ro + k] = h;
    xs[ro + DM + k] = h;
    xs[ro + 2 * DM + k] = lo;
}

// ---------------- flash attention on tensor cores (bf16 mma) ----------------
// grid (SS/64, NH, BB), 128 threads (4 warps). Warp w owns 16 q-rows.
// S accum fragments recycled directly as PV A-fragments (FA2 style).
#define ASTRIDE 72   // bf16 elems per smem row (144B, conflict-free ldmatrix)
__global__ void __launch_bounds__(128)
attn_mma_kernel(const float* __restrict__ qkv, const float* __restrict__ rpb,
                __nv_bfloat16* __restrict__ outs)
{
    __shared__ __nv_bfloat16 Qs[64 * ASTRIDE];
    __shared__ __nv_bfloat16 Ks[64 * ASTRIDE];
    __shared__ __nv_bfloat16 Vs[64 * ASTRIDE];
    __shared__ float rb[128];

    const int tid = threadIdx.x;
    const int lane = tid & 31;
    const int w = tid >> 5;
    const int qt = blockIdx.x, h = blockIdx.y, b = blockIdx.z;
    const int qbase = qt * 64;

    if (tid < 127) rb[tid] = rpb[tid];

    // load Q (scaled) once
    {
        int r = tid >> 1;
        int c0 = (tid & 1) * 32;
        const float* src = qkv + ((size_t)(b * SS + qbase + r)) * 3072 + h * 64 + c0;
        __nv_bfloat16* dst = &Qs[r * ASTRIDE + c0];
#pragma unroll
        for (int j = 0; j < 8; j++) {
            float4 v = *(const float4*)(src + j * 4);
            dst[j * 4 + 0] = __float2bfloat16(v.x * 0.125f);
            dst[j * 4 + 1] = __float2bfloat16(v.y * 0.125f);
            dst[j * 4 + 2] = __float2bfloat16(v.z * 0.125f);
            dst[j * 4 + 3] = __float2bfloat16(v.w * 0.125f);
        }
    }

    const uint32_t sQ = smem_u32(Qs), sK = smem_u32(Ks), sV = smem_u32(Vs);
    const uint32_t aQ = sQ + (w * 16 + (lane & 15)) * (ASTRIDE * 2) + (lane >> 4) * 16;
    const uint32_t bKV = (((lane >> 3) & 1) * 8 + (lane & 7)) * (ASTRIDE * 2) + (lane >> 4) * 16;

    float m0 = -1e30f, m1 = -1e30f, l0 = 0.f, l1 = 0.f;
    float o[8][4];
#pragma unroll
    for (int nt = 0; nt < 8; nt++)
#pragma unroll
        for (int j = 0; j < 4; j++) o[nt][j] = 0.f;

    const int r0 = lane >> 2;
    const int cql = (lane & 3) * 2;
    const int qg0 = qbase + w * 16 + r0;

    for (int kt = 0; kt < 16; kt++) {
        __syncthreads();
        // load K,V tile (f32 -> bf16)
        {
            int r = tid >> 1;
            int c0 = (tid & 1) * 32;
            size_t base = ((size_t)(b * SS + kt * 64 + r)) * 3072 + h * 64 + c0;
            const float* srcK = qkv + base + 1024;
            const float* srcV = qkv + base + 2048;
            __nv_bfloat16* dK = &Ks[r * ASTRIDE + c0];
            __nv_bfloat16* dV = &Vs[r * ASTRIDE + c0];
#pragma unroll
            for (int j = 0; j < 8; j++) {
                float4 vk = *(const float4*)(srcK + j * 4);
                float4 vv = *(const float4*)(srcV + j * 4);
                *(__nv_bfloat162*)(dK + j * 4)     = __floats2bfloat162_rn(vk.x, vk.y);
                *(__nv_bfloat162*)(dK + j * 4 + 2) = __floats2bfloat162_rn(vk.z, vk.w);
                *(__nv_bfloat162*)(dV + j * 4)     = __floats2bfloat162_rn(vv.x, vv.y);
                *(__nv_bfloat162*)(dV + j * 4 + 2) = __floats2bfloat162_rn(vv.z, vv.w);
            }
        }
        __syncthreads();

        // S = Q K^T  (16x64 per warp)
        float s[8][4];
#pragma unroll
        for (int nt = 0; nt < 8; nt++)
#pragma unroll
            for (int j = 0; j < 4; j++) s[nt][j] = 0.f;
#pragma unroll
        for (int k16 = 0; k16 < 4; k16++) {
            uint32_t a0, a1, a2, a3;
            LDM_X4(a0, a1, a2, a3, aQ + k16 * 32);
#pragma unroll
            for (int np = 0; np < 4; np++) {
                uint32_t b0, b1, b2, b3;
                LDM_X4(b0, b1, b2, b3, sK + bKV + np * (16 * ASTRIDE * 2) + k16 * 32);
                MMA_BF16(s[np * 2],     a0, a1, a2, a3, b0, b2);
                MMA_BF16(s[np * 2 + 1], a0, a1, a2, a3, b1, b3);
            }
        }

        // rel-pos bias + row maxes
        const int kb = kt * 64 + cql;
        float mt0 = -1e30f, mt1 = -1e30f;
#pragma unroll
        for (int nt = 0; nt < 8; nt++) {
            int kg = kb + nt * 8;
            int i00 = min(max(qg0 - kg + 63, 0), 126);
            int i01 = min(max(qg0 - kg + 62, 0), 126);
            int i10 = min(max(qg0 - kg + 71, 0), 126);
            int i11 = min(max(qg0 - kg + 70, 0), 126);
            s[nt][0] += rb[i00]; s[nt][1] += rb[i01];
            s[nt][2] += rb[i10]; s[nt][3] += rb[i11];
            mt0 = fmaxf(mt0, fmaxf(s[nt][0], s[nt][1]));
            mt1 = fmaxf(mt1, fmaxf(s[nt][2], s[nt][3]));
        }
        mt0 = fmaxf(mt0, __shfl_xor_sync(0xffffffffu, mt0, 1));
        mt0 = fmaxf(mt0, __shfl_xor_sync(0xffffffffu, mt0, 2));
        mt1 = fmaxf(mt1, __shfl_xor_sync(0xffffffffu, mt1, 1));
        mt1 = fmaxf(mt1, __shfl_xor_sync(0xffffffffu, mt1, 2));

        float mn0 = fmaxf(m0, mt0), mn1 = fmaxf(m1, mt1);
        float c0f = __expf(m0 - mn0), c1f = __expf(m1 - mn1);
        float ls0 = 0.f, ls1 = 0.f;
        uint32_t pa[4][4];
#pragma unroll
        for (int nt = 0; nt < 8; nt++) {
            float p0 = __expf(s[nt][0] - mn0);
            float p1 = __expf(s[nt][1] - mn0);
            float p2 = __expf(s[nt][2] - mn1);
            float p3 = __expf(s[nt][3] - mn1);
            ls0 += p0 + p1; ls1 += p2 + p3;
            uint32_t lo = pack_bf162(p0, p1);
            uint32_t hi = pack_bf162(p2, p3);
            if ((nt & 1) == 0) { pa[nt >> 1][0] = lo; pa[nt >> 1][1] = hi; }
            else               { pa[nt >> 1][2] = lo; pa[nt >> 1][3] = hi; }
        }
        ls0 += __shfl_xor_sync(0xffffffffu, ls0, 1);
        ls0 += __shfl_xor_sync(0xffffffffu, ls0, 2);
        ls1 += __shfl_xor_sync(0xffffffffu, ls1, 1);
        ls1 += __shfl_xor_sync(0xffffffffu, ls1, 2);
        l0 = l0 * c0f + ls0;
        l1 = l1 * c1f + ls1;
        m0 = mn0; m1 = mn1;
#pragma unroll
        for (int nt = 0; nt < 8; nt++) {
            o[nt][0] *= c0f; o[nt][1] *= c0f;
            o[nt][2] *= c1f; o[nt][3] *= c1f;
        }

        // O += P V
#pragma unroll
        for (int kk = 0; kk < 4; kk++) {
#pragma unroll
            for (int dt = 0; dt < 4; dt++) {
                uint32_t b0, b1, b2, b3;
                LDM_X4T(b0, b1, b2, b3, sV + bKV + kk * (16 * ASTRIDE * 2) + dt * 32);
                MMA_BF16(o[dt * 2],     pa[kk][0], pa[kk][1], pa[kk][2], pa[kk][3], b0, b1);
                MMA_BF16(o[dt * 2 + 1], pa[kk][0], pa[kk][1], pa[kk][2], pa[kk][3], b2, b3);
            }
        }
    }

    // epilogue: normalize + hi/hi/lo split write
    const float inv0 = 1.f / l0, inv1 = 1.f / l1;
    const int colb = h * 64 + cql;
#pragma unroll
    for (int nt = 0; nt < 8; nt++) {
        int col = colb + nt * 8;
#pragma unroll
        for (int half = 0; half < 2; half++) {
            float inv = half ? inv1 : inv0;
            float v0 = o[nt][half * 2 + 0] * inv;
            float v1 = o[nt][half * 2 + 1] * inv;
            int row = qbase + w * 16 + r0 + half * 8;
            size_t ro = (size_t)(b * SS + row) * KP3;
            __nv_bfloat16 h0 = __float2bfloat16(v0);
            __nv_bfloat16 h1 = __float2bfloat16(v1);
            __nv_bfloat162 hp; hp.x = h0; hp.y = h1;
            __nv_bfloat162 lp;
            lp.x = __float2bfloat16(v0 - __bfloat162float(h0));
            lp.y = __float2bfloat16(v1 - __bfloat162float(h1));
            *(__nv_bfloat162*)&outs[ro + col]          = hp;
            *(__nv_bfloat162*)&outs[ro + DM + col]     = hp;
            *(__nv_bfloat162*)&outs[ro + 2 * DM + col] = lp;
        }
    }
}

// ---------------- residual + layernorm ----------------
template <int SPLIT>
__global__ void __launch_bounds__(256)
ln_res_kernel(const float* __restrict__ a, const float* __restrict__ r,
              const float* __restrict__ g, const float* __restrict__ bt,
              float* __restrict__ out, __nv_bfloat16* __restrict__ outs)
{
    __shared__ float red[8];
    const int row = blockIdx.x;
    const int tid = threadIdx.x;
    const float* pa = a + (size_t)row * DM;
    const float* pr = r + (size_t)row * DM;

    float v[4];
    float sum = 0.f;
#pragma unroll
    for (int j = 0; j < 4; j++) {
        int c = tid + j * 256;
        v[j] = pa[c] + pr[c];
        sum += v[j];
    }
#pragma unroll
    for (int o = 16; o > 0; o >>= 1) sum += __shfl_xor_sync(0xffffffffu, sum, o);
    if ((tid & 31) == 0) red[tid >> 5] = sum;
    __syncthreads();
    float tot = 0.f;
#pragma unroll
    for (int ww = 0; ww < 8; ww++) tot += red[ww];
    const float mean = tot * (1.f / (float)DM);

    float sq = 0.f;
#pragma unroll
    for (int j = 0; j < 4; j++) { float dd = v[j] - mean; sq += dd * dd; }
    __syncthreads();
#pragma unroll
    for (int o = 16; o > 0; o >>= 1) sq += __shfl_xor_sync(0xffffffffu, sq, o);
    if ((tid & 31) == 0) red[tid >> 5] = sq;
    __syncthreads();
    float vtot = 0.f;
#pragma unroll
    for (int ww = 0; ww < 8; ww++) vtot += red[ww];
    const float inv = rsqrtf(vtot * (1.f / (float)DM) + 1e-5f);

#pragma unroll
    for (int j = 0; j < 4; j++) {
        int c = tid + j * 256;
        float o = (v[j] - mean) * inv * g[c] + bt[c];
        out[(size_t)row * DM + c] = o;
        if (SPLIT) {
            __nv_bfloat16 h = __float2bfloat16(o);
            __nv_bfloat16 lo = __float2bfloat16(o - __bfloat162float(h));
            size_t ro = (size_t)row * KP3;
            outs[ro + c] = h;
            outs[ro + DM + c] = h;
            outs[ro + 2 * DM + c] = lo;
        }
    }
}

// ---------------- host ----------------
extern "C" void kernel_launch(void* const* d_in, const int* in_sizes, int n_in,
                              void* d_out, int out_size)
{
    const float* x     = (const float*)d_in[0];
    const float* se    = (const float*)d_in[1];
    const float* qkv_w = (const float*)d_in[2];
    const float* qkv_b = (const float*)d_in[3];
    const float* out_w = (const float*)d_in[4];
    const float* out_b = (const float*)d_in[5];
    const float* rpb   = (const float*)d_in[6];
    const float* w1    = (const float*)d_in[7];
    const float* b1    = (const float*)d_in[8];
    const float* w2    = (const float*)d_in[9];
    const float* b2    = (const float*)d_in[10];
    const float* ln1g  = (const float*)d_in[11];
    const float* ln1b  = (const float*)d_in[12];
    const float* ln2g  = (const float*)d_in[13];
    const float* ln2b  = (const float*)d_in[14];
    const int*   ts    = (const int*)d_in[15];
    float* out = (float*)d_out;

    float *x0, *qkv, *proj, *x1, *ffn;
    __nv_bfloat16 *x0s, *attns, *x1s, *hs, *wqkvs, *wouts, *w1s, *w2s;
    cudaGetSymbolAddress((void**)&x0,   g_x0);
    cudaGetSymbolAddress((void**)&qkv,  g_qkv);
    cudaGetSymbolAddress((void**)&proj, g_proj);
    cudaGetSymbolAddress((void**)&x1,   g_x1);
    cudaGetSymbolAddress((void**)&ffn,  g_ffn);
    cudaGetSymbolAddress((void**)&x0s,   g_x0s);
    cudaGetSymbolAddress((void**)&attns, g_attns);
    cudaGetSymbolAddress((void**)&x1s,   g_x1s);
    cudaGetSymbolAddress((void**)&hs,    g_hs);
    cudaGetSymbolAddress((void**)&wqkvs, g_wqkvs);
    cudaGetSymbolAddress((void**)&wouts, g_wouts);
    cudaGetSymbolAddress((void**)&w1s,   g_w1s);
    cudaGetSymbolAddress((void**)&w2s,   g_w2s);

    cudaFuncSetAttribute(gemm_mma<0>, cudaFuncAttributeMaxDynamicSharedMemorySize, GSMEM);
    cudaFuncSetAttribute(gemm_mma<1>, cudaFuncAttributeMaxDynamicSharedMemorySize, GSMEM);

    wconv_kernel<<<dim3(3 * DM / 32, DM / 32),  dim3(32, 8)>>>(qkv_w, wqkvs, DM, 3 * DM);
    wconv_kernel<<<dim3(DM / 32, DM / 32),      dim3(32, 8)>>>(out_w, wouts, DM, DM);
    wconv_kernel<<<dim3(DFF / 32, DM / 32),     dim3(32, 8)>>>(w1, w1s, DM, DFF);
    wconv_kernel<<<dim3(DM / 32, DFF / 32),     dim3(32, 8)>>>(w2, w2s, DFF, DM);

    add_step_kernel<<<(MTOK * DM) / 256, 256>>>(x, se, ts, x0, x0s);

    gemm_mma<0><<<dim3(3 * DM / 128, MTOK / 128), 256, GSMEM>>>(
        x0s, wqkvs, qkv_b, qkv, nullptr, 3 * DM, KP3, 0);

    attn_mma_kernel<<<dim3(SS / 64, NH, BB), 128>>>(qkv, rpb, attns);

    gemm_mma<0><<<dim3(DM / 128, MTOK / 128), 256, GSMEM>>>(
        attns, wouts, out_b, proj, nullptr, DM, KP3, 0);

    ln_res_kernel<1><<<MTOK, 256>>>(x0, proj, ln1g, ln1b, x1, x1s);

    gemm_mma<1><<<dim3(DFF / 128, MTOK / 128), 256, GSMEM>>>(
        x1s, w1s, b1, nullptr, hs, DFF, KP3, DFF);

    gemm_mma<0><<<dim3(DM / 128, MTOK / 128), 256, GSMEM>>>(
        hs, w2s, b2, ffn, nullptr, DM, KP3FF, 0);

    ln_res_kernel<0><<<MTOK, 256>>>(x1, ffn, ln2g, ln2b, out, nullptr);
}

// round 7
// speedup vs baseline: 1.9302x; 1.3674x over previous
#include <cuda_runtime.h>
#include <cuda_bf16.h>
#include <cuda_fp16.h>
#include <math.h>
#include <stdint.h>

#define DM   1024
#define NH   16
#define DFF  4096
#define BB   8
#define SS   1024
#define MTOK (BB*SS)
#define KP2   (2*DM)    // 2048 (fp16 2-slab split-K)
#define KP2FF (2*DFF)   // 8192

// ---------------- scratch ----------------
__device__ float g_x0  [MTOK*DM];
__device__ float g_qkv [MTOK*3*DM];
__device__ float g_proj[MTOK*DM];
__device__ float g_x1  [MTOK*DM];
__device__ float g_ffn [MTOK*DM];
__device__ __half g_x0s  [(size_t)MTOK*KP2];
__device__ __half g_attns[(size_t)MTOK*KP2];
__device__ __half g_x1s  [(size_t)MTOK*KP2];
__device__ __half g_hs   [(size_t)MTOK*KP2FF];
__device__ __half g_wqkvs[(size_t)(3*DM)*KP2];
__device__ __half g_wouts[(size_t)DM*KP2];
__device__ __half g_w1s  [(size_t)DFF*KP2];
__device__ __half g_w2s  [(size_t)DM*KP2FF];

// ---------------- asm helpers ----------------
__device__ __forceinline__ uint32_t smem_u32(const void* p) {
    uint32_t a;
    asm("{ .reg .u64 t; cvta.to.shared.u64 t, %1; cvt.u32.u64 %0, t; }" : "=r"(a) : "l"(p));
    return a;
}
#define CP_ASYNC16(saddr, gptr) \
    asm volatile("cp.async.cg.shared.global [%0], [%1], 16;" :: "r"(saddr), "l"(gptr))
#define CP_COMMIT() asm volatile("cp.async.commit_group;" ::: "memory")
#define CP_WAIT1()  asm volatile("cp.async.wait_group 1;" ::: "memory")
#define CP_WAIT0()  asm volatile("cp.async.wait_group 0;" ::: "memory")

#define LDM_X4(r0, r1, r2, r3, a) \
    asm volatile("ldmatrix.sync.aligned.m8n8.x4.shared.b16 {%0,%1,%2,%3}, [%4];" \
                 : "=r"(r0), "=r"(r1), "=r"(r2), "=r"(r3) : "r"(a))
#define LDM_X4T(r0, r1, r2, r3, a) \
    asm volatile("ldmatrix.sync.aligned.m8n8.x4.trans.shared.b16 {%0,%1,%2,%3}, [%4];" \
                 : "=r"(r0), "=r"(r1), "=r"(r2), "=r"(r3) : "r"(a))
#define LDM_X2(r0, r1, a) \
    asm volatile("ldmatrix.sync.aligned.m8n8.x2.shared.b16 {%0,%1}, [%2];" \
                 : "=r"(r0), "=r"(r1) : "r"(a))

#define MMA_F16(d, a0, a1, a2, a3, b0, b1) \
    asm volatile("mma.sync.aligned.m16n8k16.row.col.f32.f16.f16.f32 " \
                 "{%0,%1,%2,%3}, {%4,%5,%6,%7}, {%8,%9}, {%0,%1,%2,%3};" \
                 : "+f"((d)[0]), "+f"((d)[1]), "+f"((d)[2]), "+f"((d)[3]) \
                 : "r"(a0), "r"(a1), "r"(a2), "r"(a3), "r"(b0), "r"(b1))
#define MMA_BF16(d, a0, a1, a2, a3, b0, b1) \
    asm volatile("mma.sync.aligned.m16n8k16.row.col.f32.bf16.bf16.f32 " \
                 "{%0,%1,%2,%3}, {%4,%5,%6,%7}, {%8,%9}, {%0,%1,%2,%3};" \
                 : "+f"((d)[0]), "+f"((d)[1]), "+f"((d)[2]), "+f"((d)[3]) \
                 : "r"(a0), "r"(a1), "r"(a2), "r"(a3), "r"(b0), "r"(b1))

__device__ __forceinline__ float gelu_exact(float v) {
    return 0.5f * v * (1.0f + erff(v * 0.70710678118654752f));
}
__device__ __forceinline__ uint32_t pack_bf162(float lo, float hi) {
    __nv_bfloat162 t = __floats2bfloat162_rn(lo, hi);
    return *(uint32_t*)&t;
}

// ---------------- GEMM via mma.sync (fp16, f32 accum) --------------------
// C[M,N] = A''[M,Kp] x B''t[N,Kp]. CTA 128x128, BK=32, 8 warps of 64x32.
#define STG_E   (128 * 40)
#define STG_B   (STG_E * 2)         // 10240 bytes
#define NSTAGE  3
#define GSMEM   (NSTAGE * STG_B * 2)  // 61440 bytes

template <int ACT>
__global__ void __launch_bounds__(256, 2)
gemm_mma(const __half* __restrict__ A, const __half* __restrict__ B,
         const float* __restrict__ bias, float* __restrict__ Cf,
         __half* __restrict__ Cs, int Ndim, int Kp, int cs_slab)
{
    extern __shared__ __align__(128) char smem[];
    const uint32_t sA = smem_u32(smem);
    const uint32_t sB = sA + NSTAGE * STG_B;

    const int tid  = threadIdx.x;
    const int lane = tid & 31;
    const int wid  = tid >> 5;
    const int wm   = wid & 1;
    const int wn   = wid >> 1;
    const int row0 = blockIdx.y * 128;
    const int n0   = blockIdx.x * 128;

    const int ldr0 = tid >> 2;
    const int ldkc = (tid & 3) * 16;
    const __half* gA = A + (size_t)(row0 + ldr0) * Kp;
    const __half* gB = B + (size_t)(n0  + ldr0) * Kp;

    const uint32_t aLd = sA + ((wm * 64 + (lane & 15)) * 40 + (lane >> 4) * 8) * 2;
    const uint32_t bLd = sB + ((wn * 32 + (lane & 7)) * 40 + ((lane >> 3) & 1) * 8) * 2;

    float d[4][4][4];
#pragma unroll
    for (int i = 0; i < 4; i++)
#pragma unroll
        for (int j = 0; j < 4; j++)
#pragma unroll
            for (int c = 0; c < 4; c++) d[i][j][c] = 0.f;

    const int kTiles = Kp >> 5;

#pragma unroll
    for (int s = 0; s < 2; s++) {
        const int k0 = s * 32;
#pragma unroll
        for (int i = 0; i < 2; i++) {
            int r = ldr0 + i * 64;
            uint32_t dstA = sA + s * STG_B + r * 80 + ldkc;
            uint32_t dstB = sB + s * STG_B + r * 80 + ldkc;
            CP_ASYNC16(dstA, (const char*)(gA + (size_t)i * 64 * Kp + k0) + ldkc);
            CP_ASYNC16(dstB, (const char*)(gB + (size_t)i * 64 * Kp + k0) + ldkc);
        }
        CP_COMMIT();
    }

    for (int kt = 0; kt < kTiles; kt++) {
        CP_WAIT1();
        __syncthreads();

        if (kt + 2 < kTiles) {
            const int s = (kt + 2) % NSTAGE;
            const int k0 = (kt + 2) * 32;
#pragma unroll
            for (int i = 0; i < 2; i++) {
                int r = ldr0 + i * 64;
                uint32_t dstA = sA + s * STG_B + r * 80 + ldkc;
                uint32_t dstB = sB + s * STG_B + r * 80 + ldkc;
                CP_ASYNC16(dstA, (const char*)(gA + (size_t)i * 64 * Kp + k0) + ldkc);
                CP_ASYNC16(dstB, (const char*)(gB + (size_t)i * 64 * Kp + k0) + ldkc);
            }
        }
        CP_COMMIT();

        const uint32_t aS = aLd + (kt % NSTAGE) * STG_B;
        const uint32_t bS = bLd + (kt % NSTAGE) * STG_B;
#pragma unroll
        for (int k16 = 0; k16 < 2; k16++) {
            uint32_t a[4][4], b[4][2];
#pragma unroll
            for (int mt = 0; mt < 4; mt++)
                LDM_X4(a[mt][0], a[mt][1], a[mt][2], a[mt][3],
                       aS + mt * (16 * 80) + k16 * 32);
#pragma unroll
            for (int nt = 0; nt < 4; nt++)
                LDM_X2(b[nt][0], b[nt][1], bS + nt * (8 * 80) + k16 * 32);
#pragma unroll
            for (int mt = 0; mt < 4; mt++)
#pragma unroll
                for (int nt = 0; nt < 4; nt++)
                    MMA_F16(d[mt][nt], a[mt][0], a[mt][1], a[mt][2], a[mt][3],
                            b[nt][0], b[nt][1]);
        }
    }
    CP_WAIT0();

#pragma unroll
    for (int mt = 0; mt < 4; mt++) {
#pragma unroll
        for (int half = 0; half < 2; half++) {
            const int row = row0 + wm * 64 + mt * 16 + (lane >> 2) + half * 8;
#pragma unroll
            for (int nt = 0; nt < 4; nt++) {
                const int col = n0 + wn * 32 + nt * 8 + (lane & 3) * 2;
                float v0 = d[mt][nt][half * 2 + 0] + bias[col];
                float v1 = d[mt][nt][half * 2 + 1] + bias[col + 1];
                if (ACT == 0) {
                    float2 o; o.x = v0; o.y = v1;
                    *(float2*)&Cf[(size_t)row * Ndim + col] = o;
                } else {
                    v0 = gelu_exact(v0);
                    v1 = gelu_exact(v1);
                    __half h0 = __float2half_rn(v0);
                    __half h1 = __float2half_rn(v1);
                    __half2 hp; hp.x = h0; hp.y = h1;
                    __half2 lp;
                    lp.x = __float2half_rn(v0 - __half2float(h0));
                    lp.y = __float2half_rn(v1 - __half2float(h1));
                    const size_t ro = (size_t)row * (size_t)(2 * cs_slab);
                    *(__half2*)&Cs[ro + col]           = hp;
                    *(__half2*)&Cs[ro + cs_slab + col] = lp;
                }
            }
        }
    }
}

// -------- weight transpose + fp16: W[K,N] -> Wt''[N,2K] = [hi|hi] --------
__global__ void wconv_kernel(const float* __restrict__ W, __half* __restrict__ Wt,
                             int K, int N)
{
    __shared__ float t[32][33];
    const int n0 = blockIdx.x * 32, k0 = blockIdx.y * 32;
    for (int i = threadIdx.y; i < 32; i += 8)
        t[i][threadIdx.x] = W[(size_t)(k0 + i) * N + n0 + threadIdx.x];
    __syncthreads();
    for (int i = threadIdx.y; i < 32; i += 8) {
        int n = n0 + i, k = k0 + threadIdx.x;
        float v = t[threadIdx.x][i];
        __half hv = __float2half_rn(v);
        size_t ro = (size_t)n * (size_t)(2 * K);
        Wt[ro + k] = hv;
        Wt[ro + K + k] = hv;
    }
}

// -------- add step embed + split: A'' = [hi|lo] --------
__global__ void add_step_kernel(const float* __restrict__ x, const float* __restrict__ se,
                                const int* __restrict__ ts, float* __restrict__ x0,
                                __half* __restrict__ xs)
{
    int i = blockIdx.x * blockDim.x + threadIdx.x;
    int step = ts[0];
    if (step > 15) step = 15;
    if (step < 0) step += 16;
    int k = i & (DM - 1);
    float v = x[i] + se[step * DM + k];
    x0[i] = v;
    __half h = __float2half_rn(v);
    __half lo = __float2half_rn(v - __half2float(h));
    size_t ro = (size_t)(i >> 10) * KP2;
    xs[ro + k] = h;
    xs[ro + DM + k] = lo;
}

// ---------------- flash attention on tensor cores (bf16 mma) ----------------
#define ASTRIDE 72
__global__ void __launch_bounds__(128)
attn_mma_kernel(const float* __restrict__ qkv, const float* __restrict__ rpb,
                __half* __restrict__ outs)
{
    __shared__ __nv_bfloat16 Qs[64 * ASTRIDE];
    __shared__ __nv_bfloat16 Ks[64 * ASTRIDE];
    __shared__ __nv_bfloat16 Vs[64 * ASTRIDE];
    __shared__ float rb[128];

    const int tid = threadIdx.x;
    const int lane = tid & 31;
    const int w = tid >> 5;
    const int qt = blockIdx.x, h = blockIdx.y, b = blockIdx.z;
    const int qbase = qt * 64;

    if (tid < 127) rb[tid] = rpb[tid];

    {
        int r = tid >> 1;
        int c0 = (tid & 1) * 32;
        const float* src = qkv + ((size_t)(b * SS + qbase + r)) * 3072 + h * 64 + c0;
        __nv_bfloat16* dst = &Qs[r * ASTRIDE + c0];
#pragma unroll
        for (int j = 0; j < 8; j++) {
            float4 v = *(const float4*)(src + j * 4);
            dst[j * 4 + 0] = __float2bfloat16(v.x * 0.125f);
            dst[j * 4 + 1] = __float2bfloat16(v.y * 0.125f);
            dst[j * 4 + 2] = __float2bfloat16(v.z * 0.125f);
            dst[j * 4 + 3] = __float2bfloat16(v.w * 0.125f);
        }
    }

    const uint32_t sQ = smem_u32(Qs), sK = smem_u32(Ks), sV = smem_u32(Vs);
    const uint32_t aQ = sQ + (w * 16 + (lane & 15)) * (ASTRIDE * 2) + (lane >> 4) * 16;
    const uint32_t bKV = (((lane >> 3) & 1) * 8 + (lane & 7)) * (ASTRIDE * 2) + (lane >> 4) * 16;

    float m0 = -1e30f, m1 = -1e30f, l0 = 0.f, l1 = 0.f;
    float o[8][4];
#pragma unroll
    for (int nt = 0; nt < 8; nt++)
#pragma unroll
        for (int j = 0; j < 4; j++) o[nt][j] = 0.f;

    const int r0 = lane >> 2;
    const int cql = (lane & 3) * 2;
    const int qg0 = qbase + w * 16 + r0;

    for (int kt = 0; kt < 16; kt++) {
        __syncthreads();
        {
            int r = tid >> 1;
            int c0 = (tid & 1) * 32;
            size_t base = ((size_t)(b * SS + kt * 64 + r)) * 3072 + h * 64 + c0;
            const float* srcK = qkv + base + 1024;
            const float* srcV = qkv + base + 2048;
            __nv_bfloat16* dK = &Ks[r * ASTRIDE + c0];
            __nv_bfloat16* dV = &Vs[r * ASTRIDE + c0];
#pragma unroll
            for (int j = 0; j < 8; j++) {
                float4 vk = *(const float4*)(srcK + j * 4);
                float4 vv = *(const float4*)(srcV + j * 4);
                *(__nv_bfloat162*)(dK + j * 4)     = __floats2bfloat162_rn(vk.x, vk.y);
                *(__nv_bfloat162*)(dK + j * 4 + 2) = __floats2bfloat162_rn(vk.z, vk.w);
                *(__nv_bfloat162*)(dV + j * 4)     = __floats2bfloat162_rn(vv.x, vv.y);
                *(__nv_bfloat162*)(dV + j * 4 + 2) = __floats2bfloat162_rn(vv.z, vv.w);
            }
        }
        __syncthreads();

        float s[8][4];
#pragma unroll
        for (int nt = 0; nt < 8; nt++)
#pragma unroll
            for (int j = 0; j < 4; j++) s[nt][j] = 0.f;
#pragma unroll
        for (int k16 = 0; k16 < 4; k16++) {
            uint32_t a0, a1, a2, a3;
            LDM_X4(a0, a1, a2, a3, aQ + k16 * 32);
#pragma unroll
            for (int np = 0; np < 4; np++) {
                uint32_t b0, b1, b2, b3;
                LDM_X4(b0, b1, b2, b3, sK + bKV + np * (16 * ASTRIDE * 2) + k16 * 32);
                MMA_BF16(s[np * 2],     a0, a1, a2, a3, b0, b2);
                MMA_BF16(s[np * 2 + 1], a0, a1, a2, a3, b1, b3);
            }
        }

        const int kb = kt * 64 + cql;
        float mt0 = -1e30f, mt1 = -1e30f;
#pragma unroll
        for (int nt = 0; nt < 8; nt++) {
            int kg = kb + nt * 8;
            int i00 = min(max(qg0 - kg + 63, 0), 126);
            int i01 = min(max(qg0 - kg + 62, 0), 126);
            int i10 = min(max(qg0 - kg + 71, 0), 126);
            int i11 = min(max(qg0 - kg + 70, 0), 126);
            s[nt][0] += rb[i00]; s[nt][1] += rb[i01];
            s[nt][2] += rb[i10]; s[nt][3] += rb[i11];
            mt0 = fmaxf(mt0, fmaxf(s[nt][0], s[nt][1]));
            mt1 = fmaxf(mt1, fmaxf(s[nt][2], s[nt][3]));
        }
        mt0 = fmaxf(mt0, __shfl_xor_sync(0xffffffffu, mt0, 1));
        mt0 = fmaxf(mt0, __shfl_xor_sync(0xffffffffu, mt0, 2));
        mt1 = fmaxf(mt1, __shfl_xor_sync(0xffffffffu, mt1, 1));
        mt1 = fmaxf(mt1, __shfl_xor_sync(0xffffffffu, mt1, 2));

        float mn0 = fmaxf(m0, mt0), mn1 = fmaxf(m1, mt1);
        float c0f = __expf(m0 - mn0), c1f = __expf(m1 - mn1);
        float ls0 = 0.f, ls1 = 0.f;
        uint32_t pa[4][4];
#pragma unroll
        for (int nt = 0; nt < 8; nt++) {
            float p0 = __expf(s[nt][0] - mn0);
            float p1 = __expf(s[nt][1] - mn0);
            float p2 = __expf(s[nt][2] - mn1);
            float p3 = __expf(s[nt][3] - mn1);
            ls0 += p0 + p1; ls1 += p2 + p3;
            uint32_t lo = pack_bf162(p0, p1);
            uint32_t hi = pack_bf162(p2, p3);
            if ((nt & 1) == 0) { pa[nt >> 1][0] = lo; pa[nt >> 1][1] = hi; }
            else               { pa[nt >> 1][2] = lo; pa[nt >> 1][3] = hi; }
        }
        ls0 += __shfl_xor_sync(0xffffffffu, ls0, 1);
        ls0 += __shfl_xor_sync(0xffffffffu, ls0, 2);
        ls1 += __shfl_xor_sync(0xffffffffu, ls1, 1);
        ls1 += __shfl_xor_sync(0xffffffffu, ls1, 2);
        l0 = l0 * c0f + ls0;
        l1 = l1 * c1f + ls1;
        m0 = mn0; m1 = mn1;
#pragma unroll
        for (int nt = 0; nt < 8; nt++) {
            o[nt][0] *= c0f; o[nt][1] *= c0f;
            o[nt][2] *= c1f; o[nt][3] *= c1f;
        }

#pragma unroll
        for (int kk = 0; kk < 4; kk++) {
#pragma unroll
            for (int dt = 0; dt < 4; dt++) {
                uint32_t b0, b1, b2, b3;
                LDM_X4T(b0, b1, b2, b3, sV + bKV + kk * (16 * ASTRIDE * 2) + dt * 32);
                MMA_BF16(o[dt * 2],     pa[kk][0], pa[kk][1], pa[kk][2], pa[kk][3], b0, b1);
                MMA_BF16(o[dt * 2 + 1], pa[kk][0], pa[kk][1], pa[kk][2], pa[kk][3], b2, b3);
            }
        }
    }

    const float inv0 = 1.f / l0, inv1 = 1.f / l1;
    const int colb = h * 64 + cql;
#pragma unroll
    for (int nt = 0; nt < 8; nt++) {
        int col = colb + nt * 8;
#pragma unroll
        for (int half = 0; half < 2; half++) {
            float inv = half ? inv1 : inv0;
            float v0 = o[nt][half * 2 + 0] * inv;
            float v1 = o[nt][half * 2 + 1] * inv;
            int row = qbase + w * 16 + r0 + half * 8;
            size_t ro = (size_t)(b * SS + row) * KP2;
            __half h0 = __float2half_rn(v0);
            __half h1 = __float2half_rn(v1);
            __half2 hp; hp.x = h0; hp.y = h1;
            __half2 lp;
            lp.x = __float2half_rn(v0 - __half2float(h0));
            lp.y = __float2half_rn(v1 - __half2float(h1));
            *(__half2*)&outs[ro + col]      = hp;
            *(__half2*)&outs[ro + DM + col] = lp;
        }
    }
}

// ---------------- residual + layernorm ----------------
template <int SPLIT>
__global__ void __launch_bounds__(256)
ln_res_kernel(const float* __restrict__ a, const float* __restrict__ r,
              const float* __restrict__ g, const float* __restrict__ bt,
              float* __restrict__ out, __half* __restrict__ outs)
{
    __shared__ float red[8];
    const int row = blockIdx.x;
    const int tid = threadIdx.x;
    const float* pa = a + (size_t)row * DM;
    const float* pr = r + (size_t)row * DM;

    float v[4];
    float sum = 0.f;
#pragma unroll
    for (int j = 0; j < 4; j++) {
        int c = tid + j * 256;
        v[j] = pa[c] + pr[c];
        sum += v[j];
    }
#pragma unroll
    for (int o = 16; o > 0; o >>= 1) sum += __shfl_xor_sync(0xffffffffu, sum, o);
    if ((tid & 31) == 0) red[tid >> 5] = sum;
    __syncthreads();
    float tot = 0.f;
#pragma unroll
    for (int ww = 0; ww < 8; ww++) tot += red[ww];
    const float mean = tot * (1.f / (float)DM);

    float sq = 0.f;
#pragma unroll
    for (int j = 0; j < 4; j++) { float dd = v[j] - mean; sq += dd * dd; }
    __syncthreads();
#pragma unroll
    for (int o = 16; o > 0; o >>= 1) sq += __shfl_xor_sync(0xffffffffu, sq, o);
    if ((tid & 31) == 0) red[tid >> 5] = sq;
    __syncthreads();
    float vtot = 0.f;
#pragma unroll
    for (int ww = 0; ww < 8; ww++) vtot += red[ww];
    const float inv = rsqrtf(vtot * (1.f / (float)DM) + 1e-5f);

#pragma unroll
    for (int j = 0; j < 4; j++) {
        int c = tid + j * 256;
        float o = (v[j] - mean) * inv * g[c] + bt[c];
        out[(size_t)row * DM + c] = o;
        if (SPLIT) {
            __half h = __float2half_rn(o);
            __half lo = __float2half_rn(o - __half2float(h));
            size_t ro = (size_t)row * KP2;
            outs[ro + c] = h;
            outs[ro + DM + c] = lo;
        }
    }
}

// ---------------- host ----------------
extern "C" void kernel_launch(void* const* d_in, const int* in_sizes, int n_in,
                              void* d_out, int out_size)
{
    const float* x     = (const float*)d_in[0];
    const float* se    = (const float*)d_in[1];
    const float* qkv_w = (const float*)d_in[2];
    const float* qkv_b = (const float*)d_in[3];
    const float* out_w = (const float*)d_in[4];
    const float* out_b = (const float*)d_in[5];
    const float* rpb   = (const float*)d_in[6];
    const float* w1    = (const float*)d_in[7];
    const float* b1    = (const float*)d_in[8];
    const float* w2    = (const float*)d_in[9];
    const float* b2    = (const float*)d_in[10];
    const float* ln1g  = (const float*)d_in[11];
    const float* ln1b  = (const float*)d_in[12];
    const float* ln2g  = (const float*)d_in[13];
    const float* ln2b  = (const float*)d_in[14];
    const int*   ts    = (const int*)d_in[15];
    float* out = (float*)d_out;

    float *x0, *qkv, *proj, *x1, *ffn;
    __half *x0s, *attns, *x1s, *hs, *wqkvs, *wouts, *w1s, *w2s;
    cudaGetSymbolAddress((void**)&x0,   g_x0);
    cudaGetSymbolAddress((void**)&qkv,  g_qkv);
    cudaGetSymbolAddress((void**)&proj, g_proj);
    cudaGetSymbolAddress((void**)&x1,   g_x1);
    cudaGetSymbolAddress((void**)&ffn,  g_ffn);
    cudaGetSymbolAddress((void**)&x0s,   g_x0s);
    cudaGetSymbolAddress((void**)&attns, g_attns);
    cudaGetSymbolAddress((void**)&x1s,   g_x1s);
    cudaGetSymbolAddress((void**)&hs,    g_hs);
    cudaGetSymbolAddress((void**)&wqkvs, g_wqkvs);
    cudaGetSymbolAddress((void**)&wouts, g_wouts);
    cudaGetSymbolAddress((void**)&w1s,   g_w1s);
    cudaGetSymbolAddress((void**)&w2s,   g_w2s);

    cudaFuncSetAttribute(gemm_mma<0>, cudaFuncAttributeMaxDynamicSharedMemorySize, GSMEM);
    cudaFuncSetAttribute(gemm_mma<1>, cudaFuncAttributeMaxDynamicSharedMemorySize, GSMEM);

    wconv_kernel<<<dim3(3 * DM / 32, DM / 32),  dim3(32, 8)>>>(qkv_w, wqkvs, DM, 3 * DM);
    wconv_kernel<<<dim3(DM / 32, DM / 32),      dim3(32, 8)>>>(out_w, wouts, DM, DM);
    wconv_kernel<<<dim3(DFF / 32, DM / 32),     dim3(32, 8)>>>(w1, w1s, DM, DFF);
    wconv_kernel<<<dim3(DM / 32, DFF / 32),     dim3(32, 8)>>>(w2, w2s, DFF, DM);

    add_step_kernel<<<(MTOK * DM) / 256, 256>>>(x, se, ts, x0, x0s);

    gemm_mma<0><<<dim3(3 * DM / 128, MTOK / 128), 256, GSMEM>>>(
        x0s, wqkvs, qkv_b, qkv, nullptr, 3 * DM, KP2, 0);

    attn_mma_kernel<<<dim3(SS / 64, NH, BB), 128>>>(qkv, rpb, attns);

    gemm_mma<0><<<dim3(DM / 128, MTOK / 128), 256, GSMEM>>>(
        attns, wouts, out_b, proj, nullptr, DM, KP2, 0);

    ln_res_kernel<1><<<MTOK, 256>>>(x0, proj, ln1g, ln1b, x1, x1s);

    gemm_mma<1><<<dim3(DFF / 128, MTOK / 128), 256, GSMEM>>>(
        x1s, w1s, b1, nullptr, hs, DFF, KP2, DFF);

    gemm_mma<0><<<dim3(DM / 128, MTOK / 128), 256, GSMEM>>>(
        hs, w2s, b2, ffn, nullptr, DM, KP2FF, 0);

    ln_res_kernel<0><<<MTOK, 256>>>(x1, ffn, ln2g, ln2b, out, nullptr);
}

// round 8
// speedup vs baseline: 2.9743x; 1.5409x over previous
#include <cuda_runtime.h>
#include <cuda_bf16.h>
#include <cuda_fp16.h>
#include <math.h>
#include <stdint.h>

#define DM   1024
#define NH   16
#define DFF  4096
#define BB   8
#define SS   1024
#define MTOK (BB*SS)

// ---------------- scratch ----------------
__device__ float g_x0  [MTOK*DM];
__device__ float g_qkv [MTOK*3*DM];
__device__ float g_proj[MTOK*DM];
__device__ float g_x1  [MTOK*DM];
__device__ float g_ffn [MTOK*DM];
__device__ __half g_x0s  [(size_t)MTOK*DM];
__device__ __half g_attns[(size_t)MTOK*DM];
__device__ __half g_x1s  [(size_t)MTOK*DM];
__device__ __half g_hs   [(size_t)MTOK*DFF];
__device__ __half g_wqkvs[(size_t)(3*DM)*DM];
__device__ __half g_wouts[(size_t)DM*DM];
__device__ __half g_w1s  [(size_t)DFF*DM];
__device__ __half g_w2s  [(size_t)DM*DFF];

// ---------------- asm helpers ----------------
__device__ __forceinline__ uint32_t smem_u32(const void* p) {
    uint32_t a;
    asm("{ .reg .u64 t; cvta.to.shared.u64 t, %1; cvt.u32.u64 %0, t; }" : "=r"(a) : "l"(p));
    return a;
}
#define CP_ASYNC16(saddr, gptr) \
    asm volatile("cp.async.cg.shared.global [%0], [%1], 16;" :: "r"(saddr), "l"(gptr))
#define CP_COMMIT() asm volatile("cp.async.commit_group;" ::: "memory")
#define CP_WAIT1()  asm volatile("cp.async.wait_group 1;" ::: "memory")
#define CP_WAIT0()  asm volatile("cp.async.wait_group 0;" ::: "memory")

#define LDM_X4(r0, r1, r2, r3, a) \
    asm volatile("ldmatrix.sync.aligned.m8n8.x4.shared.b16 {%0,%1,%2,%3}, [%4];" \
                 : "=r"(r0), "=r"(r1), "=r"(r2), "=r"(r3) : "r"(a))
#define LDM_X4T(r0, r1, r2, r3, a) \
    asm volatile("ldmatrix.sync.aligned.m8n8.x4.trans.shared.b16 {%0,%1,%2,%3}, [%4];" \
                 : "=r"(r0), "=r"(r1), "=r"(r2), "=r"(r3) : "r"(a))
#define LDM_X2(r0, r1, a) \
    asm volatile("ldmatrix.sync.aligned.m8n8.x2.shared.b16 {%0,%1}, [%2];" \
                 : "=r"(r0), "=r"(r1) : "r"(a))

#define MMA_F16(d, a0, a1, a2, a3, b0, b1) \
    asm volatile("mma.sync.aligned.m16n8k16.row.col.f32.f16.f16.f32 " \
                 "{%0,%1,%2,%3}, {%4,%5,%6,%7}, {%8,%9}, {%0,%1,%2,%3};" \
                 : "+f"((d)[0]), "+f"((d)[1]), "+f"((d)[2]), "+f"((d)[3]) \
                 : "r"(a0), "r"(a1), "r"(a2), "r"(a3), "r"(b0), "r"(b1))
#define MMA_BF16(d, a0, a1, a2, a3, b0, b1) \
    asm volatile("mma.sync.aligned.m16n8k16.row.col.f32.bf16.bf16.f32 " \
                 "{%0,%1,%2,%3}, {%4,%5,%6,%7}, {%8,%9}, {%0,%1,%2,%3};" \
                 : "+f"((d)[0]), "+f"((d)[1]), "+f"((d)[2]), "+f"((d)[3]) \
                 : "r"(a0), "r"(a1), "r"(a2), "r"(a3), "r"(b0), "r"(b1))

__device__ __forceinline__ float gelu_exact(float v) {
    return 0.5f * v * (1.0f + erff(v * 0.70710678118654752f));
}
__device__ __forceinline__ uint32_t pack_bf162(float lo, float hi) {
    __nv_bfloat162 t = __floats2bfloat162_rn(lo, hi);
    return *(uint32_t*)&t;
}

// ---------------- GEMM via mma.sync (fp16, f32 accum) --------------------
// C[M,N] = A[M,Kp] x Bt[N,Kp]. CTA 128x128, BK=32, 8 warps of 64x32.
#define STG_E   (128 * 40)
#define STG_B   (STG_E * 2)         // 10240 bytes
#define NSTAGE  3
#define GSMEM   (NSTAGE * STG_B * 2)  // 61440 bytes

template <int ACT>
__global__ void __launch_bounds__(256, 2)
gemm_mma(const __half* __restrict__ A, const __half* __restrict__ B,
         const float* __restrict__ bias, float* __restrict__ Cf,
         __half* __restrict__ Cs, int Ndim, int Kp)
{
    extern __shared__ __align__(128) char smem[];
    const uint32_t sA = smem_u32(smem);
    const uint32_t sB = sA + NSTAGE * STG_B;

    const int tid  = threadIdx.x;
    const int lane = tid & 31;
    const int wid  = tid >> 5;
    const int wm   = wid & 1;
    const int wn   = wid >> 1;
    const int row0 = blockIdx.y * 128;
    const int n0   = blockIdx.x * 128;

    const int ldr0 = tid >> 2;
    const int ldkc = (tid & 3) * 16;
    const __half* gA = A + (size_t)(row0 + ldr0) * Kp;
    const __half* gB = B + (size_t)(n0  + ldr0) * Kp;

    const uint32_t aLd = sA + ((wm * 64 + (lane & 15)) * 40 + (lane >> 4) * 8) * 2;
    const uint32_t bLd = sB + ((wn * 32 + (lane & 7)) * 40 + ((lane >> 3) & 1) * 8) * 2;

    float d[4][4][4];
#pragma unroll
    for (int i = 0; i < 4; i++)
#pragma unroll
        for (int j = 0; j < 4; j++)
#pragma unroll
            for (int c = 0; c < 4; c++) d[i][j][c] = 0.f;

    const int kTiles = Kp >> 5;

#pragma unroll
    for (int s = 0; s < 2; s++) {
        const int k0 = s * 32;
#pragma unroll
        for (int i = 0; i < 2; i++) {
            int r = ldr0 + i * 64;
            uint32_t dstA = sA + s * STG_B + r * 80 + ldkc;
            uint32_t dstB = sB + s * STG_B + r * 80 + ldkc;
            CP_ASYNC16(dstA, (const char*)(gA + (size_t)i * 64 * Kp + k0) + ldkc);
            CP_ASYNC16(dstB, (const char*)(gB + (size_t)i * 64 * Kp + k0) + ldkc);
        }
        CP_COMMIT();
    }

    for (int kt = 0; kt < kTiles; kt++) {
        CP_WAIT1();
        __syncthreads();

        if (kt + 2 < kTiles) {
            const int s = (kt + 2) % NSTAGE;
            const int k0 = (kt + 2) * 32;
#pragma unroll
            for (int i = 0; i < 2; i++) {
                int r = ldr0 + i * 64;
                uint32_t dstA = sA + s * STG_B + r * 80 + ldkc;
                uint32_t dstB = sB + s * STG_B + r * 80 + ldkc;
                CP_ASYNC16(dstA, (const char*)(gA + (size_t)i * 64 * Kp + k0) + ldkc);
                CP_ASYNC16(dstB, (const char*)(gB + (size_t)i * 64 * Kp + k0) + ldkc);
            }
        }
        CP_COMMIT();

        const uint32_t aS = aLd + (kt % NSTAGE) * STG_B;
        const uint32_t bS = bLd + (kt % NSTAGE) * STG_B;
#pragma unroll
        for (int k16 = 0; k16 < 2; k16++) {
            uint32_t a[4][4], b[4][2];
#pragma unroll
            for (int mt = 0; mt < 4; mt++)
                LDM_X4(a[mt][0], a[mt][1], a[mt][2], a[mt][3],
                       aS + mt * (16 * 80) + k16 * 32);
#pragma unroll
            for (int nt = 0; nt < 4; nt++)
                LDM_X2(b[nt][0], b[nt][1], bS + nt * (8 * 80) + k16 * 32);
#pragma unroll
            for (int mt = 0; mt < 4; mt++)
#pragma unroll
                for (int nt = 0; nt < 4; nt++)
                    MMA_F16(d[mt][nt], a[mt][0], a[mt][1], a[mt][2], a[mt][3],
                            b[nt][0], b[nt][1]);
        }
    }
    CP_WAIT0();

#pragma unroll
    for (int mt = 0; mt < 4; mt++) {
#pragma unroll
        for (int half = 0; half < 2; half++) {
            const int row = row0 + wm * 64 + mt * 16 + (lane >> 2) + half * 8;
#pragma unroll
            for (int nt = 0; nt < 4; nt++) {
                const int col = n0 + wn * 32 + nt * 8 + (lane & 3) * 2;
                float v0 = d[mt][nt][half * 2 + 0] + bias[col];
                float v1 = d[mt][nt][half * 2 + 1] + bias[col + 1];
                if (ACT == 0) {
                    float2 o; o.x = v0; o.y = v1;
                    *(float2*)&Cf[(size_t)row * Ndim + col] = o;
                } else {
                    v0 = gelu_exact(v0);
                    v1 = gelu_exact(v1);
                    __half2 hp;
                    hp.x = __float2half_rn(v0);
                    hp.y = __float2half_rn(v1);
                    *(__half2*)&Cs[(size_t)row * Ndim + col] = hp;
                }
            }
        }
    }
}

// -------- weight transpose to fp16: W[K,N] -> Wt[N,K] --------
__global__ void wconv_kernel(const float* __restrict__ W, __half* __restrict__ Wt,
                             int K, int N)
{
    __shared__ float t[32][33];
    const int n0 = blockIdx.x * 32, k0 = blockIdx.y * 32;
    for (int i = threadIdx.y; i < 32; i += 8)
        t[i][threadIdx.x] = W[(size_t)(k0 + i) * N + n0 + threadIdx.x];
    __syncthreads();
    for (int i = threadIdx.y; i < 32; i += 8) {
        int n = n0 + i, k = k0 + threadIdx.x;
        Wt[(size_t)n * K + k] = __float2half_rn(t[threadIdx.x][i]);
    }
}

// -------- add step embed; fp16 copy --------
__global__ void add_step_kernel(const float* __restrict__ x, const float* __restrict__ se,
                                const int* __restrict__ ts, float* __restrict__ x0,
                                __half* __restrict__ xs)
{
    int i = blockIdx.x * blockDim.x + threadIdx.x;
    int step = ts[0];
    if (step > 15) step = 15;
    if (step < 0) step += 16;
    int k = i & (DM - 1);
    float v = x[i] + se[step * DM + k];
    x0[i] = v;
    xs[i] = __float2half_rn(v);
}

// ---------------- flash attention on tensor cores (bf16 mma) ----------------
#define ASTRIDE 72
__global__ void __launch_bounds__(128)
attn_mma_kernel(const float* __restrict__ qkv, const float* __restrict__ rpb,
                __half* __restrict__ outs)
{
    __shared__ __nv_bfloat16 Qs[64 * ASTRIDE];
    __shared__ __nv_bfloat16 Ks[64 * ASTRIDE];
    __shared__ __nv_bfloat16 Vs[64 * ASTRIDE];
    __shared__ float rb[128];

    const int tid = threadIdx.x;
    const int lane = tid & 31;
    const int w = tid >> 5;
    const int qt = blockIdx.x, h = blockIdx.y, b = blockIdx.z;
    const int qbase = qt * 64;

    if (tid < 127) rb[tid] = rpb[tid];

    {
        int r = tid >> 1;
        int c0 = (tid & 1) * 32;
        const float* src = qkv + ((size_t)(b * SS + qbase + r)) * 3072 + h * 64 + c0;
        __nv_bfloat16* dst = &Qs[r * ASTRIDE + c0];
#pragma unroll
        for (int j = 0; j < 8; j++) {
            float4 v = *(const float4*)(src + j * 4);
            dst[j * 4 + 0] = __float2bfloat16(v.x * 0.125f);
            dst[j * 4 + 1] = __float2bfloat16(v.y * 0.125f);
            dst[j * 4 + 2] = __float2bfloat16(v.z * 0.125f);
            dst[j * 4 + 3] = __float2bfloat16(v.w * 0.125f);
        }
    }

    const uint32_t sQ = smem_u32(Qs), sK = smem_u32(Ks), sV = smem_u32(Vs);
    const uint32_t aQ = sQ + (w * 16 + (lane & 15)) * (ASTRIDE * 2) + (lane >> 4) * 16;
    const uint32_t bKV = (((lane >> 3) & 1) * 8 + (lane & 7)) * (ASTRIDE * 2) + (lane >> 4) * 16;

    float m0 = -1e30f, m1 = -1e30f, l0 = 0.f, l1 = 0.f;
    float o[8][4];
#pragma unroll
    for (int nt = 0; nt < 8; nt++)
#pragma unroll
        for (int j = 0; j < 4; j++) o[nt][j] = 0.f;

    const int r0 = lane >> 2;
    const int cql = (lane & 3) * 2;
    const int qg0 = qbase + w * 16 + r0;

    for (int kt = 0; kt < 16; kt++) {
        __syncthreads();
        {
            int r = tid >> 1;
            int c0 = (tid & 1) * 32;
            size_t base = ((size_t)(b * SS + kt * 64 + r)) * 3072 + h * 64 + c0;
            const float* srcK = qkv + base + 1024;
            const float* srcV = qkv + base + 2048;
            __nv_bfloat16* dK = &Ks[r * ASTRIDE + c0];
            __nv_bfloat16* dV = &Vs[r * ASTRIDE + c0];
#pragma unroll
            for (int j = 0; j < 8; j++) {
                float4 vk = *(const float4*)(srcK + j * 4);
                float4 vv = *(const float4*)(srcV + j * 4);
                *(__nv_bfloat162*)(dK + j * 4)     = __floats2bfloat162_rn(vk.x, vk.y);
                *(__nv_bfloat162*)(dK + j * 4 + 2) = __floats2bfloat162_rn(vk.z, vk.w);
                *(__nv_bfloat162*)(dV + j * 4)     = __floats2bfloat162_rn(vv.x, vv.y);
                *(__nv_bfloat162*)(dV + j * 4 + 2) = __floats2bfloat162_rn(vv.z, vv.w);
            }
        }
        __syncthreads();

        float s[8][4];
#pragma unroll
        for (int nt = 0; nt < 8; nt++)
#pragma unroll
            for (int j = 0; j < 4; j++) s[nt][j] = 0.f;
#pragma unroll
        for (int k16 = 0; k16 < 4; k16++) {
            uint32_t a0, a1, a2, a3;
            LDM_X4(a0, a1, a2, a3, aQ + k16 * 32);
#pragma unroll
            for (int np = 0; np < 4; np++) {
                uint32_t b0, b1, b2, b3;
                LDM_X4(b0, b1, b2, b3, sK + bKV + np * (16 * ASTRIDE * 2) + k16 * 32);
                MMA_BF16(s[np * 2],     a0, a1, a2, a3, b0, b2);
                MMA_BF16(s[np * 2 + 1], a0, a1, a2, a3, b1, b3);
            }
        }

        const int kb = kt * 64 + cql;
        float mt0 = -1e30f, mt1 = -1e30f;
#pragma unroll
        for (int nt = 0; nt < 8; nt++) {
            int kg = kb + nt * 8;
            int i00 = min(max(qg0 - kg + 63, 0), 126);
            int i01 = min(max(qg0 - kg + 62, 0), 126);
            int i10 = min(max(qg0 - kg + 71, 0), 126);
            int i11 = min(max(qg0 - kg + 70, 0), 126);
            s[nt][0] += rb[i00]; s[nt][1] += rb[i01];
            s[nt][2] += rb[i10]; s[nt][3] += rb[i11];
            mt0 = fmaxf(mt0, fmaxf(s[nt][0], s[nt][1]));
            mt1 = fmaxf(mt1, fmaxf(s[nt][2], s[nt][3]));
        }
        mt0 = fmaxf(mt0, __shfl_xor_sync(0xffffffffu, mt0, 1));
        mt0 = fmaxf(mt0, __shfl_xor_sync(0xffffffffu, mt0, 2));
        mt1 = fmaxf(mt1, __shfl_xor_sync(0xffffffffu, mt1, 1));
        mt1 = fmaxf(mt1, __shfl_xor_sync(0xffffffffu, mt1, 2));

        float mn0 = fmaxf(m0, mt0), mn1 = fmaxf(m1, mt1);
        float c0f = __expf(m0 - mn0), c1f = __expf(m1 - mn1);
        float ls0 = 0.f, ls1 = 0.f;
        uint32_t pa[4][4];
#pragma unroll
        for (int nt = 0; nt < 8; nt++) {
            float p0 = __expf(s[nt][0] - mn0);
            float p1 = __expf(s[nt][1] - mn0);
            float p2 = __expf(s[nt][2] - mn1);
            float p3 = __expf(s[nt][3] - mn1);
            ls0 += p0 + p1; ls1 += p2 + p3;
            uint32_t lo = pack_bf162(p0, p1);
            uint32_t hi = pack_bf162(p2, p3);
            if ((nt & 1) == 0) { pa[nt >> 1][0] = lo; pa[nt >> 1][1] = hi; }
            else               { pa[nt >> 1][2] = lo; pa[nt >> 1][3] = hi; }
        }
        ls0 += __shfl_xor_sync(0xffffffffu, ls0, 1);
        ls0 += __shfl_xor_sync(0xffffffffu, ls0, 2);
        ls1 += __shfl_xor_sync(0xffffffffu, ls1, 1);
        ls1 += __shfl_xor_sync(0xffffffffu, ls1, 2);
        l0 = l0 * c0f + ls0;
        l1 = l1 * c1f + ls1;
        m0 = mn0; m1 = mn1;
#pragma unroll
        for (int nt = 0; nt < 8; nt++) {
            o[nt][0] *= c0f; o[nt][1] *= c0f;
            o[nt][2] *= c1f; o[nt][3] *= c1f;
        }

#pragma unroll
        for (int kk = 0; kk < 4; kk++) {
#pragma unroll
            for (int dt = 0; dt < 4; dt++) {
                uint32_t b0, b1, b2, b3;
                LDM_X4T(b0, b1, b2, b3, sV + bKV + kk * (16 * ASTRIDE * 2) + dt * 32);
                MMA_BF16(o[dt * 2],     pa[kk][0], pa[kk][1], pa[kk][2], pa[kk][3], b0, b1);
                MMA_BF16(o[dt * 2 + 1], pa[kk][0], pa[kk][1], pa[kk][2], pa[kk][3], b2, b3);
            }
        }
    }

    const float inv0 = 1.f / l0, inv1 = 1.f / l1;
    const int colb = h * 64 + cql;
#pragma unroll
    for (int nt = 0; nt < 8; nt++) {
        int col = colb + nt * 8;
#pragma unroll
        for (int half = 0; half < 2; half++) {
            float inv = half ? inv1 : inv0;
            float v0 = o[nt][half * 2 + 0] * inv;
            float v1 = o[nt][half * 2 + 1] * inv;
            int row = qbase + w * 16 + r0 + half * 8;
            __half2 hp;
            hp.x = __float2half_rn(v0);
            hp.y = __float2half_rn(v1);
            *(__half2*)&outs[(size_t)(b * SS + row) * DM + col] = hp;
        }
    }
}

// ---------------- residual + layernorm ----------------
template <int SPLIT>
__global__ void __launch_bounds__(256)
ln_res_kernel(const float* __restrict__ a, const float* __restrict__ r,
              const float* __restrict__ g, const float* __restrict__ bt,
              float* __restrict__ out, __half* __restrict__ outs)
{
    __shared__ float red[8];
    const int row = blockIdx.x;
    const int tid = threadIdx.x;
    const float* pa = a + (size_t)row * DM;
    const float* pr = r + (size_t)row * DM;

    float v[4];
    float sum = 0.f;
#pragma unroll
    for (int j = 0; j < 4; j++) {
        int c = tid + j * 256;
        v[j] = pa[c] + pr[c];
        sum += v[j];
    }
#pragma unroll
    for (int o = 16; o > 0; o >>= 1) sum += __shfl_xor_sync(0xffffffffu, sum, o);
    if ((tid & 31) == 0) red[tid >> 5] = sum;
    __syncthreads();
    float tot = 0.f;
#pragma unroll
    for (int ww = 0; ww < 8; ww++) tot += red[ww];
    const float mean = tot * (1.f / (float)DM);

    float sq = 0.f;
#pragma unroll
    for (int j = 0; j < 4; j++) { float dd = v[j] - mean; sq += dd * dd; }
    __syncthreads();
#pragma unroll
    for (int o = 16; o > 0; o >>= 1) sq += __shfl_xor_sync(0xffffffffu, sq, o);
    if ((tid & 31) == 0) red[tid >> 5] = sq;
    __syncthreads();
    float vtot = 0.f;
#pragma unroll
    for (int ww = 0; ww < 8; ww++) vtot += red[ww];
    const float inv = rsqrtf(vtot * (1.f / (float)DM) + 1e-5f);

#pragma unroll
    for (int j = 0; j < 4; j++) {
        int c = tid + j * 256;
        float o = (v[j] - mean) * inv * g[c] + bt[c];
        out[(size_t)row * DM + c] = o;
        if (SPLIT)
            outs[(size_t)row * DM + c] = __float2half_rn(o);
    }
}

// ---------------- host ----------------
extern "C" void kernel_launch(void* const* d_in, const int* in_sizes, int n_in,
                              void* d_out, int out_size)
{
    const float* x     = (const float*)d_in[0];
    const float* se    = (const float*)d_in[1];
    const float* qkv_w = (const float*)d_in[2];
    const float* qkv_b = (const float*)d_in[3];
    const float* out_w = (const float*)d_in[4];
    const float* out_b = (const float*)d_in[5];
    const float* rpb   = (const float*)d_in[6];
    const float* w1    = (const float*)d_in[7];
    const float* b1    = (const float*)d_in[8];
    const float* w2    = (const float*)d_in[9];
    const float* b2    = (const float*)d_in[10];
    const float* ln1g  = (const float*)d_in[11];
    const float* ln1b  = (const float*)d_in[12];
    const float* ln2g  = (const float*)d_in[13];
    const float* ln2b  = (const float*)d_in[14];
    const int*   ts    = (const int*)d_in[15];
    float* out = (float*)d_out;

    float *x0, *qkv, *proj, *x1, *ffn;
    __half *x0s, *attns, *x1s, *hs, *wqkvs, *wouts, *w1s, *w2s;
    cudaGetSymbolAddress((void**)&x0,   g_x0);
    cudaGetSymbolAddress((void**)&qkv,  g_qkv);
    cudaGetSymbolAddress((void**)&proj, g_proj);
    cudaGetSymbolAddress((void**)&x1,   g_x1);
    cudaGetSymbolAddress((void**)&ffn,  g_ffn);
    cudaGetSymbolAddress((void**)&x0s,   g_x0s);
    cudaGetSymbolAddress((void**)&attns, g_attns);
    cudaGetSymbolAddress((void**)&x1s,   g_x1s);
    cudaGetSymbolAddress((void**)&hs,    g_hs);
    cudaGetSymbolAddress((void**)&wqkvs, g_wqkvs);
    cudaGetSymbolAddress((void**)&wouts, g_wouts);
    cudaGetSymbolAddress((void**)&w1s,   g_w1s);
    cudaGetSymbolAddress((void**)&w2s,   g_w2s);

    cudaFuncSetAttribute(gemm_mma<0>, cudaFuncAttributeMaxDynamicSharedMemorySize, GSMEM);
    cudaFuncSetAttribute(gemm_mma<1>, cudaFuncAttributeMaxDynamicSharedMemorySize, GSMEM);

    wconv_kernel<<<dim3(3 * DM / 32, DM / 32),  dim3(32, 8)>>>(qkv_w, wqkvs, DM, 3 * DM);
    wconv_kernel<<<dim3(DM / 32, DM / 32),      dim3(32, 8)>>>(out_w, wouts, DM, DM);
    wconv_kernel<<<dim3(DFF / 32, DM / 32),     dim3(32, 8)>>>(w1, w1s, DM, DFF);
    wconv_kernel<<<dim3(DM / 32, DFF / 32),     dim3(32, 8)>>>(w2, w2s, DFF, DM);

    add_step_kernel<<<(MTOK * DM) / 256, 256>>>(x, se, ts, x0, x0s);

    gemm_mma<0><<<dim3(3 * DM / 128, MTOK / 128), 256, GSMEM>>>(
        x0s, wqkvs, qkv_b, qkv, nullptr, 3 * DM, DM);

    attn_mma_kernel<<<dim3(SS / 64, NH, BB), 128>>>(qkv, rpb, attns);

    gemm_mma<0><<<dim3(DM / 128, MTOK / 128), 256, GSMEM>>>(
        attns, wouts, out_b, proj, nullptr, DM, DM);

    ln_res_kernel<1><<<MTOK, 256>>>(x0, proj, ln1g, ln1b, x1, x1s);

    gemm_mma<1><<<dim3(DFF / 128, MTOK / 128), 256, GSMEM>>>(
        x1s, w1s, b1, nullptr, hs, DFF, DM);

    gemm_mma<0><<<dim3(DM / 128, MTOK / 128), 256, GSMEM>>>(
        hs, w2s, b2, ffn, nullptr, DM, DFF);

    ln_res_kernel<0><<<MTOK, 256>>>(x1, ffn, ln2g, ln2b, out, nullptr);
}

// round 9
// speedup vs baseline: 3.7508x; 1.2611x over previous
#include <cuda_runtime.h>
#include <cuda_bf16.h>
#include <cuda_fp16.h>
#include <math.h>
#include <stdint.h>

#define DM   1024
#define NH   16
#define DFF  4096
#define BB   8
#define SS   1024
#define MTOK (BB*SS)

// ---------------- scratch ----------------
__device__ float g_x0  [MTOK*DM];
__device__ __nv_bfloat16 g_qkvh[(size_t)MTOK*3*DM];
__device__ float g_proj[MTOK*DM];
__device__ float g_x1  [MTOK*DM];
__device__ float g_ffn [MTOK*DM];
__device__ __half g_x0s  [(size_t)MTOK*DM];
__device__ __half g_attns[(size_t)MTOK*DM];
__device__ __half g_x1s  [(size_t)MTOK*DM];
__device__ __half g_hs   [(size_t)MTOK*DFF];
__device__ __half g_wqkvs[(size_t)(3*DM)*DM];
__device__ __half g_wouts[(size_t)DM*DM];
__device__ __half g_w1s  [(size_t)DFF*DM];
__device__ __half g_w2s  [(size_t)DM*DFF];

// ---------------- asm helpers ----------------
__device__ __forceinline__ uint32_t smem_u32(const void* p) {
    uint32_t a;
    asm("{ .reg .u64 t; cvta.to.shared.u64 t, %1; cvt.u32.u64 %0, t; }" : "=r"(a) : "l"(p));
    return a;
}
#define CP_ASYNC16(saddr, gptr) \
    asm volatile("cp.async.cg.shared.global [%0], [%1], 16;" :: "r"(saddr), "l"(gptr))
#define CP_COMMIT() asm volatile("cp.async.commit_group;" ::: "memory")
#define CP_WAIT1()  asm volatile("cp.async.wait_group 1;" ::: "memory")
#define CP_WAIT0()  asm volatile("cp.async.wait_group 0;" ::: "memory")

#define LDM_X4(r0, r1, r2, r3, a) \
    asm volatile("ldmatrix.sync.aligned.m8n8.x4.shared.b16 {%0,%1,%2,%3}, [%4];" \
                 : "=r"(r0), "=r"(r1), "=r"(r2), "=r"(r3) : "r"(a))
#define LDM_X4T(r0, r1, r2, r3, a) \
    asm volatile("ldmatrix.sync.aligned.m8n8.x4.trans.shared.b16 {%0,%1,%2,%3}, [%4];" \
                 : "=r"(r0), "=r"(r1), "=r"(r2), "=r"(r3) : "r"(a))
#define LDM_X2(r0, r1, a) \
    asm volatile("ldmatrix.sync.aligned.m8n8.x2.shared.b16 {%0,%1}, [%2];" \
                 : "=r"(r0), "=r"(r1) : "r"(a))

#define MMA_F16(d, a0, a1, a2, a3, b0, b1) \
    asm volatile("mma.sync.aligned.m16n8k16.row.col.f32.f16.f16.f32 " \
                 "{%0,%1,%2,%3}, {%4,%5,%6,%7}, {%8,%9}, {%0,%1,%2,%3};" \
                 : "+f"((d)[0]), "+f"((d)[1]), "+f"((d)[2]), "+f"((d)[3]) \
                 : "r"(a0), "r"(a1), "r"(a2), "r"(a3), "r"(b0), "r"(b1))
#define MMA_BF16(d, a0, a1, a2, a3, b0, b1) \
    asm volatile("mma.sync.aligned.m16n8k16.row.col.f32.bf16.bf16.f32 " \
                 "{%0,%1,%2,%3}, {%4,%5,%6,%7}, {%8,%9}, {%0,%1,%2,%3};" \
                 : "+f"((d)[0]), "+f"((d)[1]), "+f"((d)[2]), "+f"((d)[3]) \
                 : "r"(a0), "r"(a1), "r"(a2), "r"(a3), "r"(b0), "r"(b1))

__device__ __forceinline__ float gelu_exact(float v) {
    return 0.5f * v * (1.0f + erff(v * 0.70710678118654752f));
}
__device__ __forceinline__ uint32_t pack_bf162(float lo, float hi) {
    __nv_bfloat162 t = __floats2bfloat162_rn(lo, hi);
    return *(uint32_t*)&t;
}

// ---------------- GEMM via mma.sync (fp16, f32 accum) --------------------
// ACT=0: f32 out (+bias). ACT=1: half out, gelu(+bias). ACT=2: bf16 out (+bias),
//        cols<1024 scaled by 0.125 (Q pre-scaling for attention).
#define STG_E   (128 * 40)
#define STG_B   (STG_E * 2)
#define NSTAGE  3
#define GSMEM   (NSTAGE * STG_B * 2)

template <int ACT>
__global__ void __launch_bounds__(256, 2)
gemm_mma(const __half* __restrict__ A, const __half* __restrict__ B,
         const float* __restrict__ bias, float* __restrict__ Cf,
         void* __restrict__ Cx, int Ndim, int Kp)
{
    extern __shared__ __align__(128) char smem[];
    const uint32_t sA = smem_u32(smem);
    const uint32_t sB = sA + NSTAGE * STG_B;

    const int tid  = threadIdx.x;
    const int lane = tid & 31;
    const int wid  = tid >> 5;
    const int wm   = wid & 1;
    const int wn   = wid >> 1;
    const int row0 = blockIdx.y * 128;
    const int n0   = blockIdx.x * 128;

    const int ldr0 = tid >> 2;
    const int ldkc = (tid & 3) * 16;
    const __half* gA = A + (size_t)(row0 + ldr0) * Kp;
    const __half* gB = B + (size_t)(n0  + ldr0) * Kp;

    const uint32_t aLd = sA + ((wm * 64 + (lane & 15)) * 40 + (lane >> 4) * 8) * 2;
    const uint32_t bLd = sB + ((wn * 32 + (lane & 7)) * 40 + ((lane >> 3) & 1) * 8) * 2;

    float d[4][4][4];
#pragma unroll
    for (int i = 0; i < 4; i++)
#pragma unroll
        for (int j = 0; j < 4; j++)
#pragma unroll
            for (int c = 0; c < 4; c++) d[i][j][c] = 0.f;

    const int kTiles = Kp >> 5;

#pragma unroll
    for (int s = 0; s < 2; s++) {
        const int k0 = s * 32;
#pragma unroll
        for (int i = 0; i < 2; i++) {
            int r = ldr0 + i * 64;
            uint32_t dstA = sA + s * STG_B + r * 80 + ldkc;
            uint32_t dstB = sB + s * STG_B + r * 80 + ldkc;
            CP_ASYNC16(dstA, (const char*)(gA + (size_t)i * 64 * Kp + k0) + ldkc);
            CP_ASYNC16(dstB, (const char*)(gB + (size_t)i * 64 * Kp + k0) + ldkc);
        }
        CP_COMMIT();
    }

    for (int kt = 0; kt < kTiles; kt++) {
        CP_WAIT1();
        __syncthreads();

        if (kt + 2 < kTiles) {
            const int s = (kt + 2) % NSTAGE;
            const int k0 = (kt + 2) * 32;
#pragma unroll
            for (int i = 0; i < 2; i++) {
                int r = ldr0 + i * 64;
                uint32_t dstA = sA + s * STG_B + r * 80 + ldkc;
                uint32_t dstB = sB + s * STG_B + r * 80 + ldkc;
                CP_ASYNC16(dstA, (const char*)(gA + (size_t)i * 64 * Kp + k0) + ldkc);
                CP_ASYNC16(dstB, (const char*)(gB + (size_t)i * 64 * Kp + k0) + ldkc);
            }
        }
        CP_COMMIT();

        const uint32_t aS = aLd + (kt % NSTAGE) * STG_B;
        const uint32_t bS = bLd + (kt % NSTAGE) * STG_B;
#pragma unroll
        for (int k16 = 0; k16 < 2; k16++) {
            uint32_t a[4][4], b[4][2];
#pragma unroll
            for (int mt = 0; mt < 4; mt++)
                LDM_X4(a[mt][0], a[mt][1], a[mt][2], a[mt][3],
                       aS + mt * (16 * 80) + k16 * 32);
#pragma unroll
            for (int nt = 0; nt < 4; nt++)
                LDM_X2(b[nt][0], b[nt][1], bS + nt * (8 * 80) + k16 * 32);
#pragma unroll
            for (int mt = 0; mt < 4; mt++)
#pragma unroll
                for (int nt = 0; nt < 4; nt++)
                    MMA_F16(d[mt][nt], a[mt][0], a[mt][1], a[mt][2], a[mt][3],
                            b[nt][0], b[nt][1]);
        }
    }
    CP_WAIT0();

#pragma unroll
    for (int mt = 0; mt < 4; mt++) {
#pragma unroll
        for (int half = 0; half < 2; half++) {
            const int row = row0 + wm * 64 + mt * 16 + (lane >> 2) + half * 8;
#pragma unroll
            for (int nt = 0; nt < 4; nt++) {
                const int col = n0 + wn * 32 + nt * 8 + (lane & 3) * 2;
                float v0 = d[mt][nt][half * 2 + 0] + bias[col];
                float v1 = d[mt][nt][half * 2 + 1] + bias[col + 1];
                if (ACT == 0) {
                    float2 o; o.x = v0; o.y = v1;
                    *(float2*)&Cf[(size_t)row * Ndim + col] = o;
                } else if (ACT == 1) {
                    v0 = gelu_exact(v0);
                    v1 = gelu_exact(v1);
                    __half2 hp;
                    hp.x = __float2half_rn(v0);
                    hp.y = __float2half_rn(v1);
                    *(__half2*)&((__half*)Cx)[(size_t)row * Ndim + col] = hp;
                } else {
                    const float sc = (col < 1024) ? 0.125f : 1.0f;
                    __nv_bfloat162 hp = __floats2bfloat162_rn(v0 * sc, v1 * sc);
                    *(__nv_bfloat162*)&((__nv_bfloat16*)Cx)[(size_t)row * Ndim + col] = hp;
                }
            }
        }
    }
}

// -------- weight transpose to fp16: W[K,N] -> Wt[N,K] --------
__global__ void wconv_kernel(const float* __restrict__ W, __half* __restrict__ Wt,
                             int K, int N)
{
    __shared__ float t[32][33];
    const int n0 = blockIdx.x * 32, k0 = blockIdx.y * 32;
    for (int i = threadIdx.y; i < 32; i += 8)
        t[i][threadIdx.x] = W[(size_t)(k0 + i) * N + n0 + threadIdx.x];
    __syncthreads();
    for (int i = threadIdx.y; i < 32; i += 8) {
        int n = n0 + i, k = k0 + threadIdx.x;
        Wt[(size_t)n * K + k] = __float2half_rn(t[threadIdx.x][i]);
    }
}

// -------- add step embed; fp16 copy --------
__global__ void add_step_kernel(const float* __restrict__ x, const float* __restrict__ se,
                                const int* __restrict__ ts, float* __restrict__ x0,
                                __half* __restrict__ xs)
{
    int i = blockIdx.x * blockDim.x + threadIdx.x;
    int step = ts[0];
    if (step > 15) step = 15;
    if (step < 0) step += 16;
    int k = i & (DM - 1);
    float v = x[i] + se[step * DM + k];
    x0[i] = v;
    xs[i] = __float2half_rn(v);
}

// ---------------- flash attention on tensor cores (bf16 in, bf16 mma) -----------
// qkvh: bf16 [token, 3072], Q pre-scaled. K/V tiles double-buffered via cp.async.
#define ASTRIDE 72
#define KVB (64 * ASTRIDE * 2)   // bytes per K or V stage: 9216
__global__ void __launch_bounds__(128)
attn_mma_kernel(const __nv_bfloat16* __restrict__ qkvh, const float* __restrict__ rpb,
                __half* __restrict__ outs)
{
    __shared__ __nv_bfloat16 Qs[64 * ASTRIDE];
    __shared__ __nv_bfloat16 Kst[2][64 * ASTRIDE];
    __shared__ __nv_bfloat16 Vst[2][64 * ASTRIDE];
    __shared__ float rb[128];

    const int tid = threadIdx.x;
    const int lane = tid & 31;
    const int w = tid >> 5;
    const int qt = blockIdx.x, h = blockIdx.y, b = blockIdx.z;
    const int qbase = qt * 64;

    if (tid < 127) rb[tid] = rpb[tid];

    // Q copy (pre-scaled bf16): 64 rows x 64 cols
    {
        int r = tid >> 1;
        int c0 = (tid & 1) * 32;
        const uint4* src = (const uint4*)(qkvh + ((size_t)(b * SS + qbase + r)) * 3072 + h * 64 + c0);
        uint4* dst = (uint4*)&Qs[r * ASTRIDE + c0];
#pragma unroll
        for (int j = 0; j < 4; j++) dst[j] = src[j];
    }

    const uint32_t sQ = smem_u32(Qs);
    const uint32_t sK0 = smem_u32(Kst);
    const uint32_t sV0 = smem_u32(Vst);
    const uint32_t aQ = sQ + (w * 16 + (lane & 15)) * (ASTRIDE * 2) + (lane >> 4) * 16;
    const uint32_t bKV = (((lane >> 3) & 1) * 8 + (lane & 7)) * (ASTRIDE * 2) + (lane >> 4) * 16;

    // K/V tile loader via cp.async (16B chunks; 512 chunks per tensor / 128 thr = 4 each)
    auto load_kv = [&](int kt, int st) {
#pragma unroll
        for (int j = 0; j < 4; j++) {
            int id = tid + 128 * j;
            int r = id >> 3;
            int cb = (id & 7) * 8;
            const char* gsrc = (const char*)(qkvh + ((size_t)(b * SS + kt * 64 + r)) * 3072 + h * 64 + cb);
            CP_ASYNC16(sK0 + st * KVB + r * (ASTRIDE * 2) + cb * 2, gsrc + 2048);  // +1024 elems
            CP_ASYNC16(sV0 + st * KVB + r * (ASTRIDE * 2) + cb * 2, gsrc + 4096);  // +2048 elems
        }
        CP_COMMIT();
    };

    load_kv(0, 0);

    float m0 = -1e30f, m1 = -1e30f, l0 = 0.f, l1 = 0.f;
    float o[8][4];
#pragma unroll
    for (int nt = 0; nt < 8; nt++)
#pragma unroll
        for (int j = 0; j < 4; j++) o[nt][j] = 0.f;

    const int r0 = lane >> 2;
    const int cql = (lane & 3) * 2;
    const int qg0 = qbase + w * 16 + r0;

    for (int kt = 0; kt < 16; kt++) {
        const int st = kt & 1;
        if (kt + 1 < 16) {
            load_kv(kt + 1, st ^ 1);
            CP_WAIT1();
        } else {
            CP_WAIT0();
        }
        __syncthreads();   // stage st data visible to all warps

        const uint32_t sK = sK0 + st * KVB;
        const uint32_t sV = sV0 + st * KVB;

        // S = Q K^T (16x64 per warp)
        float s[8][4];
#pragma unroll
        for (int nt = 0; nt < 8; nt++)
#pragma unroll
            for (int j = 0; j < 4; j++) s[nt][j] = 0.f;
#pragma unroll
        for (int k16 = 0; k16 < 4; k16++) {
            uint32_t a0, a1, a2, a3;
            LDM_X4(a0, a1, a2, a3, aQ + k16 * 32);
#pragma unroll
            for (int np = 0; np < 4; np++) {
                uint32_t b0, b1, b2, b3;
                LDM_X4(b0, b1, b2, b3, sK + bKV + np * (16 * ASTRIDE * 2) + k16 * 32);
                MMA_BF16(s[np * 2],     a0, a1, a2, a3, b0, b2);
                MMA_BF16(s[np * 2 + 1], a0, a1, a2, a3, b1, b3);
            }
        }

        const int kb = kt * 64 + cql;
        float mt0 = -1e30f, mt1 = -1e30f;
#pragma unroll
        for (int nt = 0; nt < 8; nt++) {
            int kg = kb + nt * 8;
            int i00 = min(max(qg0 - kg + 63, 0), 126);
            int i01 = min(max(qg0 - kg + 62, 0), 126);
            int i10 = min(max(qg0 - kg + 71, 0), 126);
            int i11 = min(max(qg0 - kg + 70, 0), 126);
            s[nt][0] += rb[i00]; s[nt][1] += rb[i01];
            s[nt][2] += rb[i10]; s[nt][3] += rb[i11];
            mt0 = fmaxf(mt0, fmaxf(s[nt][0], s[nt][1]));
            mt1 = fmaxf(mt1, fmaxf(s[nt][2], s[nt][3]));
        }
        mt0 = fmaxf(mt0, __shfl_xor_sync(0xffffffffu, mt0, 1));
        mt0 = fmaxf(mt0, __shfl_xor_sync(0xffffffffu, mt0, 2));
        mt1 = fmaxf(mt1, __shfl_xor_sync(0xffffffffu, mt1, 1));
        mt1 = fmaxf(mt1, __shfl_xor_sync(0xffffffffu, mt1, 2));

        float mn0 = fmaxf(m0, mt0), mn1 = fmaxf(m1, mt1);
        float c0f = __expf(m0 - mn0), c1f = __expf(m1 - mn1);
        float ls0 = 0.f, ls1 = 0.f;
        uint32_t pa[4][4];
#pragma unroll
        for (int nt = 0; nt < 8; nt++) {
            float p0 = __expf(s[nt][0] - mn0);
            float p1 = __expf(s[nt][1] - mn0);
            float p2 = __expf(s[nt][2] - mn1);
            float p3 = __expf(s[nt][3] - mn1);
            ls0 += p0 + p1; ls1 += p2 + p3;
            uint32_t lo = pack_bf162(p0, p1);
            uint32_t hi = pack_bf162(p2, p3);
            if ((nt & 1) == 0) { pa[nt >> 1][0] = lo; pa[nt >> 1][1] = hi; }
            else               { pa[nt >> 1][2] = lo; pa[nt >> 1][3] = hi; }
        }
        ls0 += __shfl_xor_sync(0xffffffffu, ls0, 1);
        ls0 += __shfl_xor_sync(0xffffffffu, ls0, 2);
        ls1 += __shfl_xor_sync(0xffffffffu, ls1, 1);
        ls1 += __shfl_xor_sync(0xffffffffu, ls1, 2);
        l0 = l0 * c0f + ls0;
        l1 = l1 * c1f + ls1;
        m0 = mn0; m1 = mn1;
#pragma unroll
        for (int nt = 0; nt < 8; nt++) {
            o[nt][0] *= c0f; o[nt][1] *= c0f;
            o[nt][2] *= c1f; o[nt][3] *= c1f;
        }

        // O += P V
#pragma unroll
        for (int kk = 0; kk < 4; kk++) {
#pragma unroll
            for (int dt = 0; dt < 4; dt++) {
                uint32_t b0, b1, b2, b3;
                LDM_X4T(b0, b1, b2, b3, sV + bKV + kk * (16 * ASTRIDE * 2) + dt * 32);
                MMA_BF16(o[dt * 2],     pa[kk][0], pa[kk][1], pa[kk][2], pa[kk][3], b0, b1);
                MMA_BF16(o[dt * 2 + 1], pa[kk][0], pa[kk][1], pa[kk][2], pa[kk][3], b2, b3);
            }
        }
        __syncthreads();   // compute done before stage st is overwritten (kt+2 prefetch)
    }

    const float inv0 = 1.f / l0, inv1 = 1.f / l1;
    const int colb = h * 64 + cql;
#pragma unroll
    for (int nt = 0; nt < 8; nt++) {
        int col = colb + nt * 8;
#pragma unroll
        for (int half = 0; half < 2; half++) {
            float inv = half ? inv1 : inv0;
            float v0 = o[nt][half * 2 + 0] * inv;
            float v1 = o[nt][half * 2 + 1] * inv;
            int row = qbase + w * 16 + r0 + half * 8;
            __half2 hp;
            hp.x = __float2half_rn(v0);
            hp.y = __float2half_rn(v1);
            *(__half2*)&outs[(size_t)(b * SS + row) * DM + col] = hp;
        }
    }
}

// ---------------- residual + layernorm ----------------
template <int SPLIT>
__global__ void __launch_bounds__(256)
ln_res_kernel(const float* __restrict__ a, const float* __restrict__ r,
              const float* __restrict__ g, const float* __restrict__ bt,
              float* __restrict__ out, __half* __restrict__ outs)
{
    __shared__ float red[8];
    const int row = blockIdx.x;
    const int tid = threadIdx.x;
    const float* pa = a + (size_t)row * DM;
    const float* pr = r + (size_t)row * DM;

    float v[4];
    float sum = 0.f;
#pragma unroll
    for (int j = 0; j < 4; j++) {
        int c = tid + j * 256;
        v[j] = pa[c] + pr[c];
        sum += v[j];
    }
#pragma unroll
    for (int o = 16; o > 0; o >>= 1) sum += __shfl_xor_sync(0xffffffffu, sum, o);
    if ((tid & 31) == 0) red[tid >> 5] = sum;
    __syncthreads();
    float tot = 0.f;
#pragma unroll
    for (int ww = 0; ww < 8; ww++) tot += red[ww];
    const float mean = tot * (1.f / (float)DM);

    float sq = 0.f;
#pragma unroll
    for (int j = 0; j < 4; j++) { float dd = v[j] - mean; sq += dd * dd; }
    __syncthreads();
#pragma unroll
    for (int o = 16; o > 0; o >>= 1) sq += __shfl_xor_sync(0xffffffffu, sq, o);
    if ((tid & 31) == 0) red[tid >> 5] = sq;
    __syncthreads();
    float vtot = 0.f;
#pragma unroll
    for (int ww = 0; ww < 8; ww++) vtot += red[ww];
    const float inv = rsqrtf(vtot * (1.f / (float)DM) + 1e-5f);

#pragma unroll
    for (int j = 0; j < 4; j++) {
        int c = tid + j * 256;
        float o = (v[j] - mean) * inv * g[c] + bt[c];
        out[(size_t)row * DM + c] = o;
        if (SPLIT)
            outs[(size_t)row * DM + c] = __float2half_rn(o);
    }
}

// ---------------- host ----------------
extern "C" void kernel_launch(void* const* d_in, const int* in_sizes, int n_in,
                              void* d_out, int out_size)
{
    const float* x     = (const float*)d_in[0];
    const float* se    = (const float*)d_in[1];
    const float* qkv_w = (const float*)d_in[2];
    const float* qkv_b = (const float*)d_in[3];
    const float* out_w = (const float*)d_in[4];
    const float* out_b = (const float*)d_in[5];
    const float* rpb   = (const float*)d_in[6];
    const float* w1    = (const float*)d_in[7];
    const float* b1    = (const float*)d_in[8];
    const float* w2    = (const float*)d_in[9];
    const float* b2    = (const float*)d_in[10];
    const float* ln1g  = (const float*)d_in[11];
    const float* ln1b  = (const float*)d_in[12];
    const float* ln2g  = (const float*)d_in[13];
    const float* ln2b  = (const float*)d_in[14];
    const int*   ts    = (const int*)d_in[15];
    float* out = (float*)d_out;

    float *x0, *proj, *x1, *ffn;
    __nv_bfloat16 *qkvh;
    __half *x0s, *attns, *x1s, *hs, *wqkvs, *wouts, *w1s, *w2s;
    cudaGetSymbolAddress((void**)&x0,   g_x0);
    cudaGetSymbolAddress((void**)&qkvh, g_qkvh);
    cudaGetSymbolAddress((void**)&proj, g_proj);
    cudaGetSymbolAddress((void**)&x1,   g_x1);
    cudaGetSymbolAddress((void**)&ffn,  g_ffn);
    cudaGetSymbolAddress((void**)&x0s,   g_x0s);
    cudaGetSymbolAddress((void**)&attns, g_attns);
    cudaGetSymbolAddress((void**)&x1s,   g_x1s);
    cudaGetSymbolAddress((void**)&hs,    g_hs);
    cudaGetSymbolAddress((void**)&wqkvs, g_wqkvs);
    cudaGetSymbolAddress((void**)&wouts, g_wouts);
    cudaGetSymbolAddress((void**)&w1s,   g_w1s);
    cudaGetSymbolAddress((void**)&w2s,   g_w2s);

    cudaFuncSetAttribute(gemm_mma<0>, cudaFuncAttributeMaxDynamicSharedMemorySize, GSMEM);
    cudaFuncSetAttribute(gemm_mma<1>, cudaFuncAttributeMaxDynamicSharedMemorySize, GSMEM);
    cudaFuncSetAttribute(gemm_mma<2>, cudaFuncAttributeMaxDynamicSharedMemorySize, GSMEM);

    wconv_kernel<<<dim3(3 * DM / 32, DM / 32),  dim3(32, 8)>>>(qkv_w, wqkvs, DM, 3 * DM);
    wconv_kernel<<<dim3(DM / 32, DM / 32),      dim3(32, 8)>>>(out_w, wouts, DM, DM);
    wconv_kernel<<<dim3(DFF / 32, DM / 32),     dim3(32, 8)>>>(w1, w1s, DM, DFF);
    wconv_kernel<<<dim3(DM / 32, DFF / 32),     dim3(32, 8)>>>(w2, w2s, DFF, DM);

    add_step_kernel<<<(MTOK * DM) / 256, 256>>>(x, se, ts, x0, x0s);

    // qkv (bf16 out, Q pre-scaled)
    gemm_mma<2><<<dim3(3 * DM / 128, MTOK / 128), 256, GSMEM>>>(
        x0s, wqkvs, qkv_b, nullptr, qkvh, 3 * DM, DM);

    attn_mma_kernel<<<dim3(SS / 64, NH, BB), 128>>>(qkvh, rpb, attns);

    gemm_mma<0><<<dim3(DM / 128, MTOK / 128), 256, GSMEM>>>(
        attns, wouts, out_b, proj, nullptr, DM, DM);

    ln_res_kernel<1><<<MTOK, 256>>>(x0, proj, ln1g, ln1b, x1, x1s);

    gemm_mma<1><<<dim3(DFF / 128, MTOK / 128), 256, GSMEM>>>(
        x1s, w1s, b1, nullptr, hs, DFF, DM);

    gemm_mma<0><<<dim3(DM / 128, MTOK / 128), 256, GSMEM>>>(
        hs, w2s, b2, ffn, nullptr, DM, DFF);

    ln_res_kernel<0><<<MTOK, 256>>>(x1, ffn, ln2g, ln2b, out, nullptr);
}

// round 10
// speedup vs baseline: 3.9701x; 1.0585x over previous
#include <cuda_runtime.h>
#include <cuda_bf16.h>
#include <cuda_fp16.h>
#include <math.h>
#include <stdint.h>

#define DM   1024
#define NH   16
#define DFF  4096
#define BB   8
#define SS   1024
#define MTOK (BB*SS)

// ---------------- scratch ----------------
__device__ float g_x0  [MTOK*DM];
__device__ __nv_bfloat16 g_qkvh[(size_t)MTOK*3*DM];
__device__ float g_proj[MTOK*DM];
__device__ float g_x1  [MTOK*DM];
__device__ float g_ffn [MTOK*DM];
__device__ __half g_x0s  [(size_t)MTOK*DM];
__device__ __half g_attns[(size_t)MTOK*DM];
__device__ __half g_x1s  [(size_t)MTOK*DM];
__device__ __half g_hs   [(size_t)MTOK*DFF];
__device__ __half g_wqkvs[(size_t)(3*DM)*DM];
__device__ __half g_wouts[(size_t)DM*DM];
__device__ __half g_w1s  [(size_t)DFF*DM];
__device__ __half g_w2s  [(size_t)DM*DFF];

// ---------------- asm helpers ----------------
__device__ __forceinline__ uint32_t smem_u32(const void* p) {
    uint32_t a;
    asm("{ .reg .u64 t; cvta.to.shared.u64 t, %1; cvt.u32.u64 %0, t; }" : "=r"(a) : "l"(p));
    return a;
}
#define CP_ASYNC16(saddr, gptr) \
    asm volatile("cp.async.cg.shared.global [%0], [%1], 16;" :: "r"(saddr), "l"(gptr))
#define CP_COMMIT() asm volatile("cp.async.commit_group;" ::: "memory")
#define CP_WAIT1()  asm volatile("cp.async.wait_group 1;" ::: "memory")
#define CP_WAIT0()  asm volatile("cp.async.wait_group 0;" ::: "memory")

#define LDM_X4(r0, r1, r2, r3, a) \
    asm volatile("ldmatrix.sync.aligned.m8n8.x4.shared.b16 {%0,%1,%2,%3}, [%4];" \
                 : "=r"(r0), "=r"(r1), "=r"(r2), "=r"(r3) : "r"(a))
#define LDM_X4T(r0, r1, r2, r3, a) \
    asm volatile("ldmatrix.sync.aligned.m8n8.x4.trans.shared.b16 {%0,%1,%2,%3}, [%4];" \
                 : "=r"(r0), "=r"(r1), "=r"(r2), "=r"(r3) : "r"(a))
#define LDM_X2(r0, r1, a) \
    asm volatile("ldmatrix.sync.aligned.m8n8.x2.shared.b16 {%0,%1}, [%2];" \
                 : "=r"(r0), "=r"(r1) : "r"(a))

#define MMA_F16(d, a0, a1, a2, a3, b0, b1) \
    asm volatile("mma.sync.aligned.m16n8k16.row.col.f32.f16.f16.f32 " \
                 "{%0,%1,%2,%3}, {%4,%5,%6,%7}, {%8,%9}, {%0,%1,%2,%3};" \
                 : "+f"((d)[0]), "+f"((d)[1]), "+f"((d)[2]), "+f"((d)[3]) \
                 : "r"(a0), "r"(a1), "r"(a2), "r"(a3), "r"(b0), "r"(b1))
#define MMA_BF16(d, a0, a1, a2, a3, b0, b1) \
    asm volatile("mma.sync.aligned.m16n8k16.row.col.f32.bf16.bf16.f32 " \
                 "{%0,%1,%2,%3}, {%4,%5,%6,%7}, {%8,%9}, {%0,%1,%2,%3};" \
                 : "+f"((d)[0]), "+f"((d)[1]), "+f"((d)[2]), "+f"((d)[3]) \
                 : "r"(a0), "r"(a1), "r"(a2), "r"(a3), "r"(b0), "r"(b1))

__device__ __forceinline__ float gelu_exact(float v) {
    return 0.5f * v * (1.0f + erff(v * 0.70710678118654752f));
}
__device__ __forceinline__ uint32_t pack_bf162(float lo, float hi) {
    __nv_bfloat162 t = __floats2bfloat162_rn(lo, hi);
    return *(uint32_t*)&t;
}

// ---------------- GEMM via mma.sync (fp16, f32 accum) --------------------
// CTA 128x128, BK=64, 3-stage cp.async pipeline, 8 warps of 64x32.
// smem rows: 64 halves + 8 pad = 144B stride (conflict-free ldmatrix).
#define ROWB    144
#define STG_B   (128 * ROWB)          // 18432 bytes per A or B stage
#define NSTAGE  3
#define GSMEM   (NSTAGE * STG_B * 2)  // 110592 bytes

template <int ACT>
__global__ void __launch_bounds__(256, 2)
gemm_mma(const __half* __restrict__ A, const __half* __restrict__ B,
         const float* __restrict__ bias, float* __restrict__ Cf,
         void* __restrict__ Cx, int Ndim, int Kp)
{
    extern __shared__ __align__(128) char smem[];
    const uint32_t sA = smem_u32(smem);
    const uint32_t sB = sA + NSTAGE * STG_B;

    const int tid  = threadIdx.x;
    const int lane = tid & 31;
    const int wid  = tid >> 5;
    const int wm   = wid & 1;
    const int wn   = wid >> 1;
    const int row0 = blockIdx.y * 128;
    const int n0   = blockIdx.x * 128;

    const uint32_t aLd = sA + (wm * 64 + (lane & 15)) * ROWB + (lane >> 4) * 16;
    const uint32_t bLd = sB + (wn * 32 + (lane & 7)) * ROWB + ((lane >> 3) & 1) * 16;

    float d[4][4][4];
#pragma unroll
    for (int i = 0; i < 4; i++)
#pragma unroll
        for (int j = 0; j < 4; j++)
#pragma unroll
            for (int c = 0; c < 4; c++) d[i][j][c] = 0.f;

    const int kTiles = Kp >> 6;   // BK=64

    // stage loader: 128 rows x 128B per tensor; 1024 16B-chunks / 256 thr = 4 each
    auto load_stage = [&](int kt, int s) {
        const int k0 = kt * 64;
        const uint32_t dA = sA + s * STG_B;
        const uint32_t dB = sB + s * STG_B;
#pragma unroll
        for (int j = 0; j < 4; j++) {
            int id = tid + 256 * j;
            int r = id >> 3;
            int cb = (id & 7) * 16;
            CP_ASYNC16(dA + r * ROWB + cb,
                       (const char*)(A + (size_t)(row0 + r) * Kp + k0) + cb);
            CP_ASYNC16(dB + r * ROWB + cb,
                       (const char*)(B + (size_t)(n0 + r) * Kp + k0) + cb);
        }
        CP_COMMIT();
    };

    load_stage(0, 0);
    load_stage(1, 1);

    for (int kt = 0; kt < kTiles; kt++) {
        CP_WAIT1();
        __syncthreads();

        if (kt + 2 < kTiles) {
            load_stage(kt + 2, (kt + 2) % NSTAGE);
        } else {
            CP_COMMIT();
        }

        const int st = kt % NSTAGE;
        const uint32_t aS = aLd + st * STG_B;
        const uint32_t bS = bLd + st * STG_B;
#pragma unroll
        for (int k16 = 0; k16 < 4; k16++) {
            uint32_t a[4][4], b[4][2];
#pragma unroll
            for (int mt = 0; mt < 4; mt++)
                LDM_X4(a[mt][0], a[mt][1], a[mt][2], a[mt][3],
                       aS + mt * (16 * ROWB) + k16 * 32);
#pragma unroll
            for (int nt = 0; nt < 4; nt++)
                LDM_X2(b[nt][0], b[nt][1], bS + nt * (8 * ROWB) + k16 * 32);
#pragma unroll
            for (int mt = 0; mt < 4; mt++)
#pragma unroll
                for (int nt = 0; nt < 4; nt++)
                    MMA_F16(d[mt][nt], a[mt][0], a[mt][1], a[mt][2], a[mt][3],
                            b[nt][0], b[nt][1]);
        }
        __syncthreads();
    }
    CP_WAIT0();

#pragma unroll
    for (int mt = 0; mt < 4; mt++) {
#pragma unroll
        for (int half = 0; half < 2; half++) {
            const int row = row0 + wm * 64 + mt * 16 + (lane >> 2) + half * 8;
#pragma unroll
            for (int nt = 0; nt < 4; nt++) {
                const int col = n0 + wn * 32 + nt * 8 + (lane & 3) * 2;
                float v0 = d[mt][nt][half * 2 + 0] + bias[col];
                float v1 = d[mt][nt][half * 2 + 1] + bias[col + 1];
                if (ACT == 0) {
                    float2 o; o.x = v0; o.y = v1;
                    *(float2*)&Cf[(size_t)row * Ndim + col] = o;
                } else if (ACT == 1) {
                    v0 = gelu_exact(v0);
                    v1 = gelu_exact(v1);
                    __half2 hp;
                    hp.x = __float2half_rn(v0);
                    hp.y = __float2half_rn(v1);
                    *(__half2*)&((__half*)Cx)[(size_t)row * Ndim + col] = hp;
                } else {
                    const float sc = (col < 1024) ? 0.125f : 1.0f;
                    __nv_bfloat162 hp = __floats2bfloat162_rn(v0 * sc, v1 * sc);
                    *(__nv_bfloat162*)&((__nv_bfloat16*)Cx)[(size_t)row * Ndim + col] = hp;
                }
            }
        }
    }
}

// -------- weight transpose to fp16: W[K,N] -> Wt[N,K] --------
__global__ void wconv_kernel(const float* __restrict__ W, __half* __restrict__ Wt,
                             int K, int N)
{
    __shared__ float t[32][33];
    const int n0 = blockIdx.x * 32, k0 = blockIdx.y * 32;
#pragma unroll
    for (int i = threadIdx.y; i < 32; i += 8)
        t[i][threadIdx.x] = W[(size_t)(k0 + i) * N + n0 + threadIdx.x];
    __syncthreads();
#pragma unroll
    for (int i = threadIdx.y; i < 32; i += 8) {
        int n = n0 + i, k = k0 + threadIdx.x;
        Wt[(size_t)n * K + k] = __float2half_rn(t[threadIdx.x][i]);
    }
}

// -------- add step embed; fp16 copy --------
__global__ void add_step_kernel(const float* __restrict__ x, const float* __restrict__ se,
                                const int* __restrict__ ts, float* __restrict__ x0,
                                __half* __restrict__ xs)
{
    int i = blockIdx.x * blockDim.x + threadIdx.x;
    int step = ts[0];
    if (step > 15) step = 15;
    if (step < 0) step += 16;
    int k = i & (DM - 1);
    float v = x[i] + se[step * DM + k];
    x0[i] = v;
    xs[i] = __float2half_rn(v);
}

// ---------------- flash attention on tensor cores (bf16 in, bf16 mma) -----------
#define ASTRIDE 72
#define KVB (64 * ASTRIDE * 2)
__global__ void __launch_bounds__(128)
attn_mma_kernel(const __nv_bfloat16* __restrict__ qkvh, const float* __restrict__ rpb,
                __half* __restrict__ outs)
{
    __shared__ __nv_bfloat16 Qs[64 * ASTRIDE];
    __shared__ __nv_bfloat16 Kst[2][64 * ASTRIDE];
    __shared__ __nv_bfloat16 Vst[2][64 * ASTRIDE];
    __shared__ float rb[128];

    const int tid = threadIdx.x;
    const int lane = tid & 31;
    const int w = tid >> 5;
    const int qt = blockIdx.x, h = blockIdx.y, b = blockIdx.z;
    const int qbase = qt * 64;

    if (tid < 127) rb[tid] = rpb[tid];

    {
        int r = tid >> 1;
        int c0 = (tid & 1) * 32;
        const uint4* src = (const uint4*)(qkvh + ((size_t)(b * SS + qbase + r)) * 3072 + h * 64 + c0);
        uint4* dst = (uint4*)&Qs[r * ASTRIDE + c0];
#pragma unroll
        for (int j = 0; j < 4; j++) dst[j] = src[j];
    }

    const uint32_t sQ = smem_u32(Qs);
    const uint32_t sK0 = smem_u32(Kst);
    const uint32_t sV0 = smem_u32(Vst);
    const uint32_t aQ = sQ + (w * 16 + (lane & 15)) * (ASTRIDE * 2) + (lane >> 4) * 16;
    const uint32_t bKV = (((lane >> 3) & 1) * 8 + (lane & 7)) * (ASTRIDE * 2) + (lane >> 4) * 16;

    auto load_kv = [&](int kt, int st) {
#pragma unroll
        for (int j = 0; j < 4; j++) {
            int id = tid + 128 * j;
            int r = id >> 3;
            int cb = (id & 7) * 8;
            const char* gsrc = (const char*)(qkvh + ((size_t)(b * SS + kt * 64 + r)) * 3072 + h * 64 + cb);
            CP_ASYNC16(sK0 + st * KVB + r * (ASTRIDE * 2) + cb * 2, gsrc + 2048);
            CP_ASYNC16(sV0 + st * KVB + r * (ASTRIDE * 2) + cb * 2, gsrc + 4096);
        }
        CP_COMMIT();
    };

    load_kv(0, 0);

    float m0 = -1e30f, m1 = -1e30f, l0 = 0.f, l1 = 0.f;
    float o[8][4];
#pragma unroll
    for (int nt = 0; nt < 8; nt++)
#pragma unroll
        for (int j = 0; j < 4; j++) o[nt][j] = 0.f;

    const int r0 = lane >> 2;
    const int cql = (lane & 3) * 2;
    const int qg0 = qbase + w * 16 + r0;

    for (int kt = 0; kt < 16; kt++) {
        const int st = kt & 1;
        if (kt + 1 < 16) {
            load_kv(kt + 1, st ^ 1);
            CP_WAIT1();
        } else {
            CP_WAIT0();
        }
        __syncthreads();

        const uint32_t sK = sK0 + st * KVB;
        const uint32_t sV = sV0 + st * KVB;

        float s[8][4];
#pragma unroll
        for (int nt = 0; nt < 8; nt++)
#pragma unroll
            for (int j = 0; j < 4; j++) s[nt][j] = 0.f;
#pragma unroll
        for (int k16 = 0; k16 < 4; k16++) {
            uint32_t a0, a1, a2, a3;
            LDM_X4(a0, a1, a2, a3, aQ + k16 * 32);
#pragma unroll
            for (int np = 0; np < 4; np++) {
                uint32_t b0, b1, b2, b3;
                LDM_X4(b0, b1, b2, b3, sK + bKV + np * (16 * ASTRIDE * 2) + k16 * 32);
                MMA_BF16(s[np * 2],     a0, a1, a2, a3, b0, b2);
                MMA_BF16(s[np * 2 + 1], a0, a1, a2, a3, b1, b3);
            }
        }

        const int kb = kt * 64 + cql;
        float mt0 = -1e30f, mt1 = -1e30f;
#pragma unroll
        for (int nt = 0; nt < 8; nt++) {
            int kg = kb + nt * 8;
            int i00 = min(max(qg0 - kg + 63, 0), 126);
            int i01 = min(max(qg0 - kg + 62, 0), 126);
            int i10 = min(max(qg0 - kg + 71, 0), 126);
            int i11 = min(max(qg0 - kg + 70, 0), 126);
            s[nt][0] += rb[i00]; s[nt][1] += rb[i01];
            s[nt][2] += rb[i10]; s[nt][3] += rb[i11];
            mt0 = fmaxf(mt0, fmaxf(s[nt][0], s[nt][1]));
            mt1 = fmaxf(mt1, fmaxf(s[nt][2], s[nt][3]));
        }
        mt0 = fmaxf(mt0, __shfl_xor_sync(0xffffffffu, mt0, 1));
        mt0 = fmaxf(mt0, __shfl_xor_sync(0xffffffffu, mt0, 2));
        mt1 = fmaxf(mt1, __shfl_xor_sync(0xffffffffu, mt1, 1));
        mt1 = fmaxf(mt1, __shfl_xor_sync(0xffffffffu, mt1, 2));

        float mn0 = fmaxf(m0, mt0), mn1 = fmaxf(m1, mt1);
        float c0f = __expf(m0 - mn0), c1f = __expf(m1 - mn1);
        float ls0 = 0.f, ls1 = 0.f;
        uint32_t pa[4][4];
#pragma unroll
        for (int nt = 0; nt < 8; nt++) {
            float p0 = __expf(s[nt][0] - mn0);
            float p1 = __expf(s[nt][1] - mn0);
            float p2 = __expf(s[nt][2] - mn1);
            float p3 = __expf(s[nt][3] - mn1);
            ls0 += p0 + p1; ls1 += p2 + p3;
            uint32_t lo = pack_bf162(p0, p1);
            uint32_t hi = pack_bf162(p2, p3);
            if ((nt & 1) == 0) { pa[nt >> 1][0] = lo; pa[nt >> 1][1] = hi; }
            else               { pa[nt >> 1][2] = lo; pa[nt >> 1][3] = hi; }
        }
        ls0 += __shfl_xor_sync(0xffffffffu, ls0, 1);
        ls0 += __shfl_xor_sync(0xffffffffu, ls0, 2);
        ls1 += __shfl_xor_sync(0xffffffffu, ls1, 1);
        ls1 += __shfl_xor_sync(0xffffffffu, ls1, 2);
        l0 = l0 * c0f + ls0;
        l1 = l1 * c1f + ls1;
        m0 = mn0; m1 = mn1;
#pragma unroll
        for (int nt = 0; nt < 8; nt++) {
            o[nt][0] *= c0f; o[nt][1] *= c0f;
            o[nt][2] *= c1f; o[nt][3] *= c1f;
        }

#pragma unroll
        for (int kk = 0; kk < 4; kk++) {
#pragma unroll
            for (int dt = 0; dt < 4; dt++) {
                uint32_t b0, b1, b2, b3;
                LDM_X4T(b0, b1, b2, b3, sV + bKV + kk * (16 * ASTRIDE * 2) + dt * 32);
                MMA_BF16(o[dt * 2],     pa[kk][0], pa[kk][1], pa[kk][2], pa[kk][3], b0, b1);
                MMA_BF16(o[dt * 2 + 1], pa[kk][0], pa[kk][1], pa[kk][2], pa[kk][3], b2, b3);
            }
        }
        __syncthreads();
    }

    const float inv0 = 1.f / l0, inv1 = 1.f / l1;
    const int colb = h * 64 + cql;
#pragma unroll
    for (int nt = 0; nt < 8; nt++) {
        int col = colb + nt * 8;
#pragma unroll
        for (int half = 0; half < 2; half++) {
            float inv = half ? inv1 : inv0;
            float v0 = o[nt][half * 2 + 0] * inv;
            float v1 = o[nt][half * 2 + 1] * inv;
            int row = qbase + w * 16 + r0 + half * 8;
            __half2 hp;
            hp.x = __float2half_rn(v0);
            hp.y = __float2half_rn(v1);
            *(__half2*)&outs[(size_t)(b * SS + row) * DM + col] = hp;
        }
    }
}

// ---------------- residual + layernorm ----------------
template <int SPLIT>
__global__ void __launch_bounds__(256)
ln_res_kernel(const float* __restrict__ a, const float* __restrict__ r,
              const float* __restrict__ g, const float* __restrict__ bt,
              float* __restrict__ out, __half* __restrict__ outs)
{
    __shared__ float red[8];
    const int row = blockIdx.x;
    const int tid = threadIdx.x;
    const float* pa = a + (size_t)row * DM;
    const float* pr = r + (size_t)row * DM;

    float v[4];
    float sum = 0.f;
#pragma unroll
    for (int j = 0; j < 4; j++) {
        int c = tid + j * 256;
        v[j] = pa[c] + pr[c];
        sum += v[j];
    }
#pragma unroll
    for (int o = 16; o > 0; o >>= 1) sum += __shfl_xor_sync(0xffffffffu, sum, o);
    if ((tid & 31) == 0) red[tid >> 5] = sum;
    __syncthreads();
    float tot = 0.f;
#pragma unroll
    for (int ww = 0; ww < 8; ww++) tot += red[ww];
    const float mean = tot * (1.f / (float)DM);

    float sq = 0.f;
#pragma unroll
    for (int j = 0; j < 4; j++) { float dd = v[j] - mean; sq += dd * dd; }
    __syncthreads();
#pragma unroll
    for (int o = 16; o > 0; o >>= 1) sq += __shfl_xor_sync(0xffffffffu, sq, o);
    if ((tid & 31) == 0) red[tid >> 5] = sq;
    __syncthreads();
    float vtot = 0.f;
#pragma unroll
    for (int ww = 0; ww < 8; ww++) vtot += red[ww];
    const float inv = rsqrtf(vtot * (1.f / (float)DM) + 1e-5f);

#pragma unroll
    for (int j = 0; j < 4; j++) {
        int c = tid + j * 256;
        float o = (v[j] - mean) * inv * g[c] + bt[c];
        out[(size_t)row * DM + c] = o;
        if (SPLIT)
            outs[(size_t)row * DM + c] = __float2half_rn(o);
    }
}

// ---------------- host ----------------
extern "C" void kernel_launch(void* const* d_in, const int* in_sizes, int n_in,
                              void* d_out, int out_size)
{
    const float* x     = (const float*)d_in[0];
    const float* se    = (const float*)d_in[1];
    const float* qkv_w = (const float*)d_in[2];
    const float* qkv_b = (const float*)d_in[3];
    const float* out_w = (const float*)d_in[4];
    const float* out_b = (const float*)d_in[5];
    const float* rpb   = (const float*)d_in[6];
    const float* w1    = (const float*)d_in[7];
    const float* b1    = (const float*)d_in[8];
    const float* w2    = (const float*)d_in[9];
    const float* b2    = (const float*)d_in[10];
    const float* ln1g  = (const float*)d_in[11];
    const float* ln1b  = (const float*)d_in[12];
    const float* ln2g  = (const float*)d_in[13];
    const float* ln2b  = (const float*)d_in[14];
    const int*   ts    = (const int*)d_in[15];
    float* out = (float*)d_out;

    float *x0, *proj, *x1, *ffn;
    __nv_bfloat16 *qkvh;
    __half *x0s, *attns, *x1s, *hs, *wqkvs, *wouts, *w1s, *w2s;
    cudaGetSymbolAddress((void**)&x0,   g_x0);
    cudaGetSymbolAddress((void**)&qkvh, g_qkvh);
    cudaGetSymbolAddress((void**)&proj, g_proj);
    cudaGetSymbolAddress((void**)&x1,   g_x1);
    cudaGetSymbolAddress((void**)&ffn,  g_ffn);
    cudaGetSymbolAddress((void**)&x0s,   g_x0s);
    cudaGetSymbolAddress((void**)&attns, g_attns);
    cudaGetSymbolAddress((void**)&x1s,   g_x1s);
    cudaGetSymbolAddress((void**)&hs,    g_hs);
    cudaGetSymbolAddress((void**)&wqkvs, g_wqkvs);
    cudaGetSymbolAddress((void**)&wouts, g_wouts);
    cudaGetSymbolAddress((void**)&w1s,   g_w1s);
    cudaGetSymbolAddress((void**)&w2s,   g_w2s);

    cudaFuncSetAttribute(gemm_mma<0>, cudaFuncAttributeMaxDynamicSharedMemorySize, GSMEM);
    cudaFuncSetAttribute(gemm_mma<1>, cudaFuncAttributeMaxDynamicSharedMemorySize, GSMEM);
    cudaFuncSetAttribute(gemm_mma<2>, cudaFuncAttributeMaxDynamicSharedMemorySize, GSMEM);

    wconv_kernel<<<dim3(3 * DM / 32, DM / 32),  dim3(32, 8)>>>(qkv_w, wqkvs, DM, 3 * DM);
    wconv_kernel<<<dim3(DM / 32, DM / 32),      dim3(32, 8)>>>(out_w, wouts, DM, DM);
    wconv_kernel<<<dim3(DFF / 32, DM / 32),     dim3(32, 8)>>>(w1, w1s, DM, DFF);
    wconv_kernel<<<dim3(DM / 32, DFF / 32),     dim3(32, 8)>>>(w2, w2s, DFF, DM);

    add_step_kernel<<<(MTOK * DM) / 256, 256>>>(x, se, ts, x0, x0s);

    gemm_mma<2><<<dim3(3 * DM / 128, MTOK / 128), 256, GSMEM>>>(
        x0s, wqkvs, qkv_b, nullptr, qkvh, 3 * DM, DM);

    attn_mma_kernel<<<dim3(SS / 64, NH, BB), 128>>>(qkvh, rpb, attns);

    gemm_mma<0><<<dim3(DM / 128, MTOK / 128), 256, GSMEM>>>(
        attns, wouts, out_b, proj, nullptr, DM, DM);

    ln_res_kernel<1><<<MTOK, 256>>>(x0, proj, ln1g, ln1b, x1, x1s);

    gemm_mma<1><<<dim3(DFF / 128, MTOK / 128), 256, GSMEM>>>(
        x1s, w1s, b1, nullptr, hs, DFF, DM);

    gemm_mma<0><<<dim3(DM / 128, MTOK / 128), 256, GSMEM>>>(
        hs, w2s, b2, ffn, nullptr, DM, DFF);

    ln_res_kernel<0><<<MTOK, 256>>>(x1, ffn, ln2g, ln2b, out, nullptr);
}